// round 1
// baseline (speedup 1.0000x reference)
#include <cuda_runtime.h>
#include <math.h>

// Problem constants
#define R_ROWS  16384   // N*C
#define SPATIAL 1024    // H*W
#define MDIM    512     // mem_dim
#define HIDDIM  512     // spatial/2

// d_out section offsets (floats)
#define OFF_OUTPUT   ((size_t)0)
#define OFF_ATTSP    ((size_t)16777216)
#define OFF_INFLAT   ((size_t)33554432)
#define OFF_MEMNORM  ((size_t)50331648)
#define OFF_ATT      ((size_t)50855936)

// Device scratch (allocation-free: __device__ globals)
__device__ float g_h[MDIM * HIDDIM];
__device__ float g_memproc[MDIM * SPATIAL];
__device__ float g_invnorm[R_ROWS];
__device__ float g_avg[32 * MDIM];

// ---------------------------------------------------------------------------
// Block reduction (works for blockDim multiple of 32, <= 1024)
// ---------------------------------------------------------------------------
template <bool MAXRED>
__device__ __forceinline__ float block_reduce(float v) {
    __shared__ float sm[32];
    __shared__ float res;
    const int lane = threadIdx.x & 31;
    const int w    = threadIdx.x >> 5;
    const int nw   = blockDim.x >> 5;
#pragma unroll
    for (int o = 16; o > 0; o >>= 1) {
        float ov = __shfl_xor_sync(0xffffffffu, v, o);
        v = MAXRED ? fmaxf(v, ov) : (v + ov);
    }
    __syncthreads();                 // protect sm reuse across calls
    if (lane == 0) sm[w] = v;
    __syncthreads();
    if (w == 0) {
        float x = (lane < nw) ? sm[lane] : (MAXRED ? -INFINITY : 0.0f);
#pragma unroll
        for (int o = 16; o > 0; o >>= 1) {
            float ov = __shfl_xor_sync(0xffffffffu, x, o);
            x = MAXRED ? fmaxf(x, ov) : (x + ov);
        }
        if (lane == 0) res = x;
    }
    __syncthreads();
    return res;
}

// ---------------------------------------------------------------------------
// GEMM (NT): C[M,N] = op( A[M,K] @ B[N,K]^T ), 128x128 tile, 8x8 per thread.
// All dims assumed multiples of 128 (M,N) and 8 (K) -- true for this problem.
// Epilogue options: per-row scale, per-col bias, relu.
// ---------------------------------------------------------------------------
template <bool RELU, bool BIAS, bool ROWSCALE>
__global__ __launch_bounds__(256) void gemm_nt(
    int M, int N, int K,
    const float* __restrict__ A,
    const float* __restrict__ B,
    float* __restrict__ C,
    const float* __restrict__ bias,
    const float* __restrict__ rowscale)
{
    __shared__ float As[8][128];
    __shared__ float Bs[8][128];
    const int tid = threadIdx.x;
    const int bm = blockIdx.y * 128;
    const int bn = blockIdx.x * 128;

    const int lr = tid >> 1;          // 0..127 (row within tile)
    const int lk = (tid & 1) * 4;     // 0 or 4 (k offset)
    const float* Ap = A + (size_t)(bm + lr) * K + lk;
    const float* Bp = B + (size_t)(bn + lr) * K + lk;

    const int ty = tid >> 4;          // 0..15
    const int tx = tid & 15;          // 0..15

    float acc[8][8];
#pragma unroll
    for (int i = 0; i < 8; i++)
#pragma unroll
        for (int j = 0; j < 8; j++) acc[i][j] = 0.0f;

    for (int k0 = 0; k0 < K; k0 += 8) {
        float4 av = *(const float4*)(Ap + k0);
        float4 bv = *(const float4*)(Bp + k0);
        __syncthreads();
        As[lk + 0][lr] = av.x; As[lk + 1][lr] = av.y;
        As[lk + 2][lr] = av.z; As[lk + 3][lr] = av.w;
        Bs[lk + 0][lr] = bv.x; Bs[lk + 1][lr] = bv.y;
        Bs[lk + 2][lr] = bv.z; Bs[lk + 3][lr] = bv.w;
        __syncthreads();
#pragma unroll
        for (int k = 0; k < 8; k++) {
            float a[8], b[8];
            *(float4*)&a[0] = *(const float4*)&As[k][ty * 4];
            *(float4*)&a[4] = *(const float4*)&As[k][64 + ty * 4];
            *(float4*)&b[0] = *(const float4*)&Bs[k][tx * 4];
            *(float4*)&b[4] = *(const float4*)&Bs[k][64 + tx * 4];
#pragma unroll
            for (int i = 0; i < 8; i++)
#pragma unroll
                for (int j = 0; j < 8; j++)
                    acc[i][j] = fmaf(a[i], b[j], acc[i][j]);
        }
    }

#pragma unroll
    for (int i = 0; i < 8; i++) {
        int row = bm + ((i < 4) ? (ty * 4 + i) : (64 + ty * 4 + (i - 4)));
        float rs = ROWSCALE ? rowscale[row] : 1.0f;
#pragma unroll
        for (int jh = 0; jh < 2; jh++) {
            int col = bn + jh * 64 + tx * 4;
            float4 v;
            v.x = acc[i][jh * 4 + 0];
            v.y = acc[i][jh * 4 + 1];
            v.z = acc[i][jh * 4 + 2];
            v.w = acc[i][jh * 4 + 3];
            if (ROWSCALE) { v.x *= rs; v.y *= rs; v.z *= rs; v.w *= rs; }
            if (BIAS) {
                v.x += bias[col + 0]; v.y += bias[col + 1];
                v.z += bias[col + 2]; v.w += bias[col + 3];
            }
            if (RELU) {
                v.x = fmaxf(v.x, 0.0f); v.y = fmaxf(v.y, 0.0f);
                v.z = fmaxf(v.z, 0.0f); v.w = fmaxf(v.w, 0.0f);
            }
            *(float4*)&C[(size_t)row * N + col] = v;
        }
    }
}

// ---------------------------------------------------------------------------
// GEMM (NN): C[M,N] = A[M,K] @ B[K,N], same tiling, no epilogue.
// ---------------------------------------------------------------------------
__global__ __launch_bounds__(256) void gemm_nn(
    int M, int N, int K,
    const float* __restrict__ A,
    const float* __restrict__ B,
    float* __restrict__ C)
{
    __shared__ float As[8][128];
    __shared__ float Bs[8][128];
    const int tid = threadIdx.x;
    const int bm = blockIdx.y * 128;
    const int bn = blockIdx.x * 128;

    const int lr = tid >> 1;
    const int lk = (tid & 1) * 4;
    const float* Ap = A + (size_t)(bm + lr) * K + lk;

    const int brow = tid >> 5;          // 0..7
    const int bcol = (tid & 31) * 4;    // 0..124
    const float* Bp = B + (size_t)brow * N + bn + bcol;

    const int ty = tid >> 4;
    const int tx = tid & 15;

    float acc[8][8];
#pragma unroll
    for (int i = 0; i < 8; i++)
#pragma unroll
        for (int j = 0; j < 8; j++) acc[i][j] = 0.0f;

    for (int k0 = 0; k0 < K; k0 += 8) {
        float4 av = *(const float4*)(Ap + k0);
        float4 bv = *(const float4*)(Bp + (size_t)k0 * N);
        __syncthreads();
        As[lk + 0][lr] = av.x; As[lk + 1][lr] = av.y;
        As[lk + 2][lr] = av.z; As[lk + 3][lr] = av.w;
        *(float4*)&Bs[brow][bcol] = bv;
        __syncthreads();
#pragma unroll
        for (int k = 0; k < 8; k++) {
            float a[8], b[8];
            *(float4*)&a[0] = *(const float4*)&As[k][ty * 4];
            *(float4*)&a[4] = *(const float4*)&As[k][64 + ty * 4];
            *(float4*)&b[0] = *(const float4*)&Bs[k][tx * 4];
            *(float4*)&b[4] = *(const float4*)&Bs[k][64 + tx * 4];
#pragma unroll
            for (int i = 0; i < 8; i++)
#pragma unroll
                for (int j = 0; j < 8; j++)
                    acc[i][j] = fmaf(a[i], b[j], acc[i][j]);
        }
    }

#pragma unroll
    for (int i = 0; i < 8; i++) {
        int row = bm + ((i < 4) ? (ty * 4 + i) : (64 + ty * 4 + (i - 4)));
#pragma unroll
        for (int jh = 0; jh < 2; jh++) {
            int col = bn + jh * 64 + tx * 4;
            float4 v;
            v.x = acc[i][jh * 4 + 0];
            v.y = acc[i][jh * 4 + 1];
            v.z = acc[i][jh * 4 + 2];
            v.w = acc[i][jh * 4 + 3];
            *(float4*)&C[(size_t)row * N + col] = v;
        }
    }
}

// ---------------------------------------------------------------------------
// Per-row 1/max(||x_r||, eps) for x rows (1024 elems each)
// ---------------------------------------------------------------------------
__global__ __launch_bounds__(256) void rowinv_kernel(const float* __restrict__ x) {
    const int row = blockIdx.x;
    const float4* p = (const float4*)(x + (size_t)row * SPATIAL);
    float4 v = p[threadIdx.x];     // 256 threads * 4 = 1024
    float s = v.x * v.x + v.y * v.y + v.z * v.z + v.w * v.w;
    float tot = block_reduce<false>(s);
    if (threadIdx.x == 0)
        g_invnorm[row] = 1.0f / fmaxf(sqrtf(tot), 1e-12f);
}

// L2-normalize rows of g_memproc -> dst (memory_norm section of d_out)
__global__ __launch_bounds__(256) void rownorm_kernel(float* __restrict__ dst) {
    const int row = blockIdx.x;
    const float4* p = (const float4*)(g_memproc + (size_t)row * SPATIAL);
    float4 v = p[threadIdx.x];
    float s = v.x * v.x + v.y * v.y + v.z * v.z + v.w * v.w;
    float tot = block_reduce<false>(s);
    float sc = 1.0f / fmaxf(sqrtf(tot), 1e-12f);
    float4 o = make_float4(v.x * sc, v.y * sc, v.z * sc, v.w * sc);
    ((float4*)(dst + (size_t)row * SPATIAL))[threadIdx.x] = o;
}

// Softmax over 512 cols, hard-shrink, L1 renorm; in place. One row per block.
__global__ __launch_bounds__(512) void softmax_shrink_kernel(float* __restrict__ S) {
    const int row = blockIdx.x;
    float* p = S + (size_t)row * MDIM;
    float v = p[threadIdx.x];
    float m = block_reduce<true>(v);
    float e = expf(v - m);
    float se = block_reduce<false>(e);
    float a = fmaxf(e / se - 0.0025f, 0.0f);
    float sa = block_reduce<false>(a);
    p[threadIdx.x] = a / fmaxf(sa, 1e-12f);
}

// att_channel_avg[n,m] = mean_c att[n*512+c, m]
__global__ __launch_bounds__(128) void chanmean_kernel(const float* __restrict__ att) {
    const int n = blockIdx.x;                         // 0..31
    const int m = blockIdx.y * 128 + threadIdx.x;     // 0..511
    const float* base = att + ((size_t)n * 512) * MDIM + m;
    float s = 0.0f;
#pragma unroll 8
    for (int c = 0; c < 512; c++) s += base[(size_t)c * MDIM];
    g_avg[n * MDIM + m] = s * (1.0f / 512.0f);
}

// att_spatial[n,m,:] = avg[n,m] broadcast over 1024 positions
__global__ __launch_bounds__(256) void bcast_kernel(float* __restrict__ dst) {
    const int nm = blockIdx.x;                        // 0..16383
    const float v = g_avg[nm];
    float4 o = make_float4(v, v, v, v);
    ((float4*)(dst + (size_t)nm * SPATIAL))[threadIdx.x] = o;
}

// ---------------------------------------------------------------------------
extern "C" void kernel_launch(void* const* d_in, const int* in_sizes, int n_in,
                              void* d_out, int out_size) {
    (void)in_sizes; (void)n_in; (void)out_size;
    const float* x      = (const float*)d_in[0];
    const float* memory = (const float*)d_in[1];
    const float* w1     = (const float*)d_in[2];
    const float* b1     = (const float*)d_in[3];
    const float* w2     = (const float*)d_in[4];
    const float* b2     = (const float*)d_in[5];

    float* out = (float*)d_out;
    float* out_output  = out + OFF_OUTPUT;
    float* out_attsp   = out + OFF_ATTSP;
    float* out_inflat  = out + OFF_INFLAT;
    float* out_memnorm = out + OFF_MEMNORM;
    float* out_att     = out + OFF_ATT;

    float *p_h, *p_mp, *p_inv;
    cudaGetSymbolAddress((void**)&p_h,   g_h);
    cudaGetSymbolAddress((void**)&p_mp,  g_memproc);
    cudaGetSymbolAddress((void**)&p_inv, g_invnorm);

    // input_flat = x (pure copy)
    cudaMemcpyAsync(out_inflat, x, (size_t)R_ROWS * SPATIAL * sizeof(float),
                    cudaMemcpyDeviceToDevice);

    // MLP over memory bank: h = relu(memory @ w1^T + b1)
    gemm_nt<true, true, false><<<dim3(HIDDIM / 128, MDIM / 128), 256>>>(
        MDIM, HIDDIM, SPATIAL, memory, w1, p_h, b1, nullptr);
    // mem_proc = relu(h @ w2^T + b2)
    gemm_nt<true, true, false><<<dim3(SPATIAL / 128, MDIM / 128), 256>>>(
        MDIM, SPATIAL, HIDDIM, p_h, w2, p_mp, b2, nullptr);
    // memory_norm = l2norm(mem_proc)  -> d_out memnorm section
    rownorm_kernel<<<MDIM, 256>>>(out_memnorm);

    // per-row inverse L2 norm of x
    rowinv_kernel<<<R_ROWS, 256>>>(x);

    // S = diag(invnorm) * (x @ memory_norm^T)  -> d_out att section
    gemm_nt<false, false, true><<<dim3(MDIM / 128, R_ROWS / 128), 256>>>(
        R_ROWS, MDIM, SPATIAL, x, out_memnorm, out_att, nullptr, p_inv);

    // softmax + shrink + L1 renorm, in place -> att
    softmax_shrink_kernel<<<R_ROWS, 512>>>(out_att);

    // output = att @ memory_norm
    gemm_nn<<<dim3(SPATIAL / 128, R_ROWS / 128), 256>>>(
        R_ROWS, SPATIAL, MDIM, out_att, out_memnorm, out_output);

    // channel-mean of att + spatial broadcast
    chanmean_kernel<<<dim3(32, MDIM / 128), 128>>>(out_att);
    bcast_kernel<<<R_ROWS, 256>>>(out_attsp);
}

// round 3
// speedup vs baseline: 1.7682x; 1.7682x over previous
#include <cuda_runtime.h>
#include <cstdint>
#include <math.h>

// Problem constants
#define R_ROWS  16384   // N*C
#define SPATIAL 1024    // H*W
#define MDIM    512     // mem_dim
#define HIDDIM  512     // spatial/2

// d_out section offsets (floats)
#define OFF_OUTPUT   ((size_t)0)
#define OFF_ATTSP    ((size_t)16777216)
#define OFF_INFLAT   ((size_t)33554432)
#define OFF_MEMNORM  ((size_t)50331648)
#define OFF_ATT      ((size_t)50855936)

// Device scratch (allocation-free)
__device__ float g_h[MDIM * HIDDIM];
__device__ float g_memproc[MDIM * SPATIAL];
__device__ float g_mnT[SPATIAL * MDIM];     // transposed memory_norm
__device__ float g_invnorm[R_ROWS];
__device__ float g_avg[32 * MDIM];

// ============================================================================
// mma.sync tf32 helpers (sm_80+ — works on base compute_103 target)
// ============================================================================
__device__ __forceinline__ void mma8(float* c, uint32_t a0, uint32_t a1,
                                     uint32_t a2, uint32_t a3,
                                     uint32_t b0, uint32_t b1) {
    asm volatile(
        "mma.sync.aligned.m16n8k8.row.col.f32.tf32.tf32.f32 "
        "{%0,%1,%2,%3}, {%4,%5,%6,%7}, {%8,%9}, {%0,%1,%2,%3};"
        : "+f"(c[0]), "+f"(c[1]), "+f"(c[2]), "+f"(c[3])
        : "r"(a0), "r"(a1), "r"(a2), "r"(a3), "r"(b0), "r"(b1));
}

__device__ __forceinline__ uint32_t tf32_hi(float x) {
    uint32_t h;
    asm("cvt.rna.tf32.f32 %0, %1;" : "=r"(h) : "f"(x));
    return h;
}
__device__ __forceinline__ void tf32_split(float x, uint32_t& hi, uint32_t& lo) {
    hi = tf32_hi(x);
    float r = x - __uint_as_float(hi);
    lo = tf32_hi(r);
}

__device__ __forceinline__ void cp16(uint32_t dst, const void* src) {
    asm volatile("cp.async.cg.shared.global [%0], [%1], 16;" :: "r"(dst), "l"(src));
}

// ============================================================================
// tf32 NT GEMM: C[M,Ntot] = op( A[M,K] @ B[Ntot,K]^T )
// CTA tile 128x128xBK32, 8 warps (warp tile 64x32), 3-stage cp.async.
// PASSES=3 -> split-tf32 (~fp32 accuracy); PASSES=1 -> plain tf32.
// M,N multiples of 128; K multiple of 32.
// ============================================================================
#define SSTRIDE 36                       // padded row stride (floats)
#define TILEF   (128 * SSTRIDE)          // 4608 floats per tile
#define STAGEF  (2 * TILEF)              // A + B per stage
#define GEMM_SMEM_BYTES (3 * STAGEF * 4) // 110592 B

template <int PASSES, bool RELU, bool BIAS, bool ROWSCALE>
__global__ void __launch_bounds__(256, 1) gemm_tc(
    int Ntot, int K,
    const float* __restrict__ A, const float* __restrict__ B,
    float* __restrict__ C,
    const float* __restrict__ bias, const float* __restrict__ rowscale)
{
    extern __shared__ float smf[];
    const uint32_t sbase = (uint32_t)__cvta_generic_to_shared(smf);
    const int tid  = threadIdx.x;
    const int wid  = tid >> 5;
    const int lane = tid & 31;
    const int wm   = wid & 1;      // 0..1 (m half)
    const int wn   = wid >> 1;     // 0..3 (n quarter)
    const int tr   = lane >> 2;    // 0..7
    const int tc   = lane & 3;     // 0..3

    const int bm = blockIdx.y * 128;
    const int bn = blockIdx.x * 128;
    const float* At = A + (size_t)bm * K;
    const float* Bt = B + (size_t)bn * K;

    const int nk = K >> 5;

    // --- async load of one stage (A 128x32 + B 128x32) ---
    auto load_stage = [&](int st, int kc) {
        const uint32_t so = sbase + (uint32_t)(st * STAGEF * 4);
#pragma unroll
        for (int i = 0; i < 4; i++) {
            int u = tid + i * 256;          // 0..1023
            int row = u >> 3;
            int seg = (u & 7) * 4;
            cp16(so + (uint32_t)((row * SSTRIDE + seg) * 4),
                 At + (size_t)row * K + kc * 32 + seg);
            cp16(so + (uint32_t)((TILEF + row * SSTRIDE + seg) * 4),
                 Bt + (size_t)row * K + kc * 32 + seg);
        }
        asm volatile("cp.async.commit_group;" ::: "memory");
    };

    float c[4][4][4];
#pragma unroll
    for (int mf = 0; mf < 4; mf++)
#pragma unroll
        for (int nf = 0; nf < 4; nf++)
#pragma unroll
            for (int q = 0; q < 4; q++) c[mf][nf][q] = 0.0f;

    load_stage(0, 0);
    load_stage(1, 1);

    for (int s = 0; s < nk; ++s) {
        if (s + 2 < nk) {
            load_stage((s + 2) % 3, s + 2);
            asm volatile("cp.async.wait_group 2;" ::: "memory");
        } else if (s + 1 < nk) {
            asm volatile("cp.async.wait_group 1;" ::: "memory");
        } else {
            asm volatile("cp.async.wait_group 0;" ::: "memory");
        }
        __syncthreads();

        const float* As = smf + (s % 3) * STAGEF;
        const float* Bs = As + TILEF;

#pragma unroll
        for (int kk = 0; kk < 4; kk++) {
            const int kb = kk * 8;
            uint32_t ah[4][4], al[4][4], bh[4][2], bl[4][2];
#pragma unroll
            for (int mf = 0; mf < 4; mf++) {
                const int r0 = wm * 64 + mf * 16 + tr;
                float a0 = As[r0 * SSTRIDE + kb + tc];
                float a1 = As[(r0 + 8) * SSTRIDE + kb + tc];
                float a2 = As[r0 * SSTRIDE + kb + tc + 4];
                float a3 = As[(r0 + 8) * SSTRIDE + kb + tc + 4];
                if (PASSES == 3) {
                    tf32_split(a0, ah[mf][0], al[mf][0]);
                    tf32_split(a1, ah[mf][1], al[mf][1]);
                    tf32_split(a2, ah[mf][2], al[mf][2]);
                    tf32_split(a3, ah[mf][3], al[mf][3]);
                } else {
                    ah[mf][0] = tf32_hi(a0); ah[mf][1] = tf32_hi(a1);
                    ah[mf][2] = tf32_hi(a2); ah[mf][3] = tf32_hi(a3);
                }
            }
#pragma unroll
            for (int nf = 0; nf < 4; nf++) {
                const int n0 = wn * 32 + nf * 8 + tr;
                float b0 = Bs[n0 * SSTRIDE + kb + tc];
                float b1 = Bs[n0 * SSTRIDE + kb + tc + 4];
                if (PASSES == 3) {
                    tf32_split(b0, bh[nf][0], bl[nf][0]);
                    tf32_split(b1, bh[nf][1], bl[nf][1]);
                } else {
                    bh[nf][0] = tf32_hi(b0); bh[nf][1] = tf32_hi(b1);
                }
            }
#pragma unroll
            for (int mf = 0; mf < 4; mf++)
#pragma unroll
                for (int nf = 0; nf < 4; nf++) {
                    mma8(c[mf][nf], ah[mf][0], ah[mf][1], ah[mf][2], ah[mf][3],
                         bh[nf][0], bh[nf][1]);
                    if (PASSES == 3) {
                        mma8(c[mf][nf], ah[mf][0], ah[mf][1], ah[mf][2], ah[mf][3],
                             bl[nf][0], bl[nf][1]);
                        mma8(c[mf][nf], al[mf][0], al[mf][1], al[mf][2], al[mf][3],
                             bh[nf][0], bh[nf][1]);
                    }
                }
        }
        __syncthreads();   // protect stage buffer reuse
    }

    // --- epilogue ---
#pragma unroll
    for (int mf = 0; mf < 4; mf++) {
        const int r0g = bm + wm * 64 + mf * 16 + tr;
        const float rs0 = ROWSCALE ? rowscale[r0g] : 1.0f;
        const float rs1 = ROWSCALE ? rowscale[r0g + 8] : 1.0f;
#pragma unroll
        for (int nf = 0; nf < 4; nf++) {
            const int cg = bn + wn * 32 + nf * 8 + 2 * tc;
            float v0 = c[mf][nf][0], v1 = c[mf][nf][1];
            float v2 = c[mf][nf][2], v3 = c[mf][nf][3];
            if (ROWSCALE) { v0 *= rs0; v1 *= rs0; v2 *= rs1; v3 *= rs1; }
            if (BIAS) {
                float bb0 = bias[cg], bb1 = bias[cg + 1];
                v0 += bb0; v1 += bb1; v2 += bb0; v3 += bb1;
            }
            if (RELU) {
                v0 = fmaxf(v0, 0.0f); v1 = fmaxf(v1, 0.0f);
                v2 = fmaxf(v2, 0.0f); v3 = fmaxf(v3, 0.0f);
            }
            *(float2*)&C[(size_t)r0g * Ntot + cg]       = make_float2(v0, v1);
            *(float2*)&C[(size_t)(r0g + 8) * Ntot + cg] = make_float2(v2, v3);
        }
    }
}

// ============================================================================
// Elementwise / reduction kernels
// ============================================================================
__device__ __forceinline__ float warp_sum(float v) {
#pragma unroll
    for (int o = 16; o > 0; o >>= 1) v += __shfl_xor_sync(0xffffffffu, v, o);
    return v;
}
__device__ __forceinline__ float warp_max(float v) {
#pragma unroll
    for (int o = 16; o > 0; o >>= 1) v = fmaxf(v, __shfl_xor_sync(0xffffffffu, v, o));
    return v;
}

// 1/max(||x_row||,eps), warp per row (row = 1024 floats)
__global__ __launch_bounds__(256) void rowinv_kernel(const float* __restrict__ x) {
    const int row  = blockIdx.x * 8 + (threadIdx.x >> 5);
    const int lane = threadIdx.x & 31;
    const float4* p = (const float4*)(x + (size_t)row * SPATIAL);
    float s = 0.0f;
#pragma unroll
    for (int i = 0; i < 8; i++) {
        float4 v = p[lane + 32 * i];
        s += v.x * v.x + v.y * v.y + v.z * v.z + v.w * v.w;
    }
    s = warp_sum(s);
    if (lane == 0) g_invnorm[row] = 1.0f / fmaxf(sqrtf(s), 1e-12f);
}

// L2-normalize rows of g_memproc -> dst
__global__ __launch_bounds__(256) void rownorm_kernel(float* __restrict__ dst) {
    __shared__ float sm[8];
    const int row  = blockIdx.x;
    const int lane = threadIdx.x & 31;
    const int w    = threadIdx.x >> 5;
    const float4* p = (const float4*)(g_memproc + (size_t)row * SPATIAL);
    float4 v = p[threadIdx.x];
    float s = v.x * v.x + v.y * v.y + v.z * v.z + v.w * v.w;
    s = warp_sum(s);
    if (lane == 0) sm[w] = s;
    __syncthreads();
    float tot = 0.0f;
#pragma unroll
    for (int i = 0; i < 8; i++) tot += sm[i];
    float sc = 1.0f / fmaxf(sqrtf(tot), 1e-12f);
    float4 o = make_float4(v.x * sc, v.y * sc, v.z * sc, v.w * sc);
    ((float4*)(dst + (size_t)row * SPATIAL))[threadIdx.x] = o;
}

// transpose src [512,1024] -> g_mnT [1024,512]
__global__ __launch_bounds__(256) void transpose_kernel(const float* __restrict__ src) {
    __shared__ float t[32][33];
    const int bx = blockIdx.x * 32;   // src col base
    const int by = blockIdx.y * 32;   // src row base
    const int x = threadIdx.x & 31;
    const int y = threadIdx.x >> 5;   // 0..7
#pragma unroll
    for (int i = 0; i < 32; i += 8)
        t[y + i][x] = src[(size_t)(by + y + i) * SPATIAL + bx + x];
    __syncthreads();
#pragma unroll
    for (int i = 0; i < 32; i += 8)
        g_mnT[(size_t)(bx + y + i) * MDIM + by + x] = t[x][y + i];
}

// softmax over 512 cols, hard shrink, L1 renorm; warp per row, in place
__global__ __launch_bounds__(256) void softmax_shrink_kernel(float* __restrict__ S) {
    const int row  = blockIdx.x * 8 + (threadIdx.x >> 5);
    const int lane = threadIdx.x & 31;
    float4* p = (float4*)(S + (size_t)row * MDIM);
    float4 v[4];
#pragma unroll
    for (int i = 0; i < 4; i++) v[i] = p[lane + 32 * i];
    float m = -INFINITY;
#pragma unroll
    for (int i = 0; i < 4; i++)
        m = fmaxf(m, fmaxf(fmaxf(v[i].x, v[i].y), fmaxf(v[i].z, v[i].w)));
    m = warp_max(m);
    float s = 0.0f;
#pragma unroll
    for (int i = 0; i < 4; i++) {
        v[i].x = expf(v[i].x - m); v[i].y = expf(v[i].y - m);
        v[i].z = expf(v[i].z - m); v[i].w = expf(v[i].w - m);
        s += v[i].x + v[i].y + v[i].z + v[i].w;
    }
    s = warp_sum(s);
    const float inv = 1.0f / s;
    float t = 0.0f;
#pragma unroll
    for (int i = 0; i < 4; i++) {
        v[i].x = fmaxf(v[i].x * inv - 0.0025f, 0.0f);
        v[i].y = fmaxf(v[i].y * inv - 0.0025f, 0.0f);
        v[i].z = fmaxf(v[i].z * inv - 0.0025f, 0.0f);
        v[i].w = fmaxf(v[i].w * inv - 0.0025f, 0.0f);
        t += v[i].x + v[i].y + v[i].z + v[i].w;
    }
    t = warp_sum(t);
    const float inv2 = 1.0f / fmaxf(t, 1e-12f);
#pragma unroll
    for (int i = 0; i < 4; i++) {
        v[i].x *= inv2; v[i].y *= inv2; v[i].z *= inv2; v[i].w *= inv2;
        p[lane + 32 * i] = v[i];
    }
}

// att_channel_avg[n,m] = mean_c att[n*512+c, m]
__global__ __launch_bounds__(128) void chanmean_kernel(const float* __restrict__ att) {
    const int n = blockIdx.x;
    const int m = blockIdx.y * 128 + threadIdx.x;
    const float* base = att + ((size_t)n * 512) * MDIM + m;
    float s = 0.0f;
#pragma unroll 8
    for (int c = 0; c < 512; c++) s += base[(size_t)c * MDIM];
    g_avg[n * MDIM + m] = s * (1.0f / 512.0f);
}

// att_spatial broadcast
__global__ __launch_bounds__(256) void bcast_kernel(float* __restrict__ dst) {
    const int nm = blockIdx.x;
    const float v = g_avg[nm];
    float4 o = make_float4(v, v, v, v);
    ((float4*)(dst + (size_t)nm * SPATIAL))[threadIdx.x] = o;
}

// ============================================================================
extern "C" void kernel_launch(void* const* d_in, const int* in_sizes, int n_in,
                              void* d_out, int out_size) {
    (void)in_sizes; (void)n_in; (void)out_size;
    const float* x      = (const float*)d_in[0];
    const float* memory = (const float*)d_in[1];
    const float* w1     = (const float*)d_in[2];
    const float* b1     = (const float*)d_in[3];
    const float* w2     = (const float*)d_in[4];
    const float* b2     = (const float*)d_in[5];

    float* out = (float*)d_out;
    float* out_output  = out + OFF_OUTPUT;
    float* out_attsp   = out + OFF_ATTSP;
    float* out_inflat  = out + OFF_INFLAT;
    float* out_memnorm = out + OFF_MEMNORM;
    float* out_att     = out + OFF_ATT;

    float *p_h, *p_mp, *p_mnT, *p_inv;
    cudaGetSymbolAddress((void**)&p_h,   g_h);
    cudaGetSymbolAddress((void**)&p_mp,  g_memproc);
    cudaGetSymbolAddress((void**)&p_mnT, g_mnT);
    cudaGetSymbolAddress((void**)&p_inv, g_invnorm);

    cudaFuncSetAttribute((const void*)gemm_tc<3, true,  true,  false>,
                         cudaFuncAttributeMaxDynamicSharedMemorySize, GEMM_SMEM_BYTES);
    cudaFuncSetAttribute((const void*)gemm_tc<3, false, false, true>,
                         cudaFuncAttributeMaxDynamicSharedMemorySize, GEMM_SMEM_BYTES);
    cudaFuncSetAttribute((const void*)gemm_tc<1, false, false, false>,
                         cudaFuncAttributeMaxDynamicSharedMemorySize, GEMM_SMEM_BYTES);

    // input_flat = x (pure copy)
    cudaMemcpyAsync(out_inflat, x, (size_t)R_ROWS * SPATIAL * sizeof(float),
                    cudaMemcpyDeviceToDevice);

    // per-row inverse L2 norm of x (independent)
    rowinv_kernel<<<R_ROWS / 8, 256>>>(x);

    // MLP: h = relu(memory @ w1^T + b1)   [512,512]  (split-tf32)
    gemm_tc<3, true, true, false><<<dim3(4, 4), 256, GEMM_SMEM_BYTES>>>(
        HIDDIM, SPATIAL, memory, w1, p_h, b1, nullptr);
    // mem_proc = relu(h @ w2^T + b2)      [512,1024] (split-tf32)
    gemm_tc<3, true, true, false><<<dim3(8, 4), 256, GEMM_SMEM_BYTES>>>(
        SPATIAL, HIDDIM, p_h, w2, p_mp, b2, nullptr);

    // memory_norm -> d_out
    rownorm_kernel<<<MDIM, 256>>>(out_memnorm);
    // mnT = transpose(memory_norm)
    transpose_kernel<<<dim3(SPATIAL / 32, MDIM / 32), 256>>>(out_memnorm);

    // S = diag(invnorm) * (x @ memory_norm^T) -> att section  (split-tf32)
    gemm_tc<3, false, false, true><<<dim3(4, R_ROWS / 128), 256, GEMM_SMEM_BYTES>>>(
        MDIM, SPATIAL, x, out_memnorm, out_att, nullptr, p_inv);

    // softmax + shrink + L1 renorm, in place
    softmax_shrink_kernel<<<R_ROWS / 8, 256>>>(out_att);

    // output = att @ mnT^T  [16384,1024]  (plain tf32, no threshold downstream)
    gemm_tc<1, false, false, false><<<dim3(8, R_ROWS / 128), 256, GEMM_SMEM_BYTES>>>(
        SPATIAL, MDIM, out_att, p_mnT, out_output, nullptr, nullptr);

    // channel-mean of att + spatial broadcast
    chanmean_kernel<<<dim3(32, MDIM / 128), 128>>>(out_att);
    bcast_kernel<<<R_ROWS, 256>>>(out_attsp);
}

// round 4
// speedup vs baseline: 2.9408x; 1.6632x over previous
#include <cuda_runtime.h>
#include <cstdint>
#include <math.h>

// Problem constants
#define R_ROWS  16384   // N*C
#define SPATIAL 1024    // H*W
#define MDIM    512     // mem_dim
#define HIDDIM  512     // spatial/2

// d_out section offsets (floats)
#define OFF_OUTPUT   ((size_t)0)
#define OFF_ATTSP    ((size_t)16777216)
#define OFF_INFLAT   ((size_t)33554432)
#define OFF_MEMNORM  ((size_t)50331648)
#define OFF_ATT      ((size_t)50855936)

// Device scratch (allocation-free)
__device__ float g_h[MDIM * HIDDIM];
__device__ float g_memproc[MDIM * SPATIAL];
__device__ float g_mnT[SPATIAL * MDIM];     // transposed memory_norm
__device__ float g_invnorm[R_ROWS];
__device__ float g_avg[32 * MDIM];

// ============================================================================
// mma.sync tf32 helpers (sm_80+ — works on base compute_103 target)
// ============================================================================
__device__ __forceinline__ void mma8(float* c, uint32_t a0, uint32_t a1,
                                     uint32_t a2, uint32_t a3,
                                     uint32_t b0, uint32_t b1) {
    asm volatile(
        "mma.sync.aligned.m16n8k8.row.col.f32.tf32.tf32.f32 "
        "{%0,%1,%2,%3}, {%4,%5,%6,%7}, {%8,%9}, {%0,%1,%2,%3};"
        : "+f"(c[0]), "+f"(c[1]), "+f"(c[2]), "+f"(c[3])
        : "r"(a0), "r"(a1), "r"(a2), "r"(a3), "r"(b0), "r"(b1));
}

__device__ __forceinline__ uint32_t tf32_hi(float x) {
    uint32_t h;
    asm("cvt.rna.tf32.f32 %0, %1;" : "=r"(h) : "f"(x));
    return h;
}
__device__ __forceinline__ void tf32_split(float x, uint32_t& hi, uint32_t& lo) {
    hi = tf32_hi(x);
    float r = x - __uint_as_float(hi);
    lo = tf32_hi(r);
}

__device__ __forceinline__ void cp16(uint32_t dst, const void* src) {
    asm volatile("cp.async.cg.shared.global [%0], [%1], 16;" :: "r"(dst), "l"(src));
}

// ============================================================================
// tf32 NT GEMM: C[M,Ntot] = op( A[M,K] @ B[Ntot,K]^T )
// CTA tile 128x128xBK32, 8 warps (warp tile 64x32), 3-stage cp.async.
// PASSES=3 -> split-tf32 (~fp32 accuracy); PASSES=1 -> plain tf32.
// M,N multiples of 128; K multiple of 32.
// ============================================================================
#define SSTRIDE 36                       // padded row stride (floats)
#define TILEF   (128 * SSTRIDE)          // 4608 floats per tile
#define STAGEF  (2 * TILEF)              // A + B per stage
#define GEMM_SMEM_BYTES (3 * STAGEF * 4) // 110592 B

template <int PASSES, bool RELU, bool BIAS, bool ROWSCALE>
__global__ void __launch_bounds__(256, 1) gemm_tc(
    int Ntot, int K,
    const float* __restrict__ A, const float* __restrict__ B,
    float* __restrict__ C,
    const float* __restrict__ bias, const float* __restrict__ rowscale)
{
    extern __shared__ float smf[];
    const uint32_t sbase = (uint32_t)__cvta_generic_to_shared(smf);
    const int tid  = threadIdx.x;
    const int wid  = tid >> 5;
    const int lane = tid & 31;
    const int wm   = wid & 1;      // 0..1 (m half)
    const int wn   = wid >> 1;     // 0..3 (n quarter)
    const int tr   = lane >> 2;    // 0..7
    const int tc   = lane & 3;     // 0..3

    const int bm = blockIdx.y * 128;
    const int bn = blockIdx.x * 128;
    const float* At = A + (size_t)bm * K;
    const float* Bt = B + (size_t)bn * K;

    const int nk = K >> 5;

    // --- async load of one stage (A 128x32 + B 128x32) ---
    auto load_stage = [&](int st, int kc) {
        const uint32_t so = sbase + (uint32_t)(st * STAGEF * 4);
#pragma unroll
        for (int i = 0; i < 4; i++) {
            int u = tid + i * 256;          // 0..1023
            int row = u >> 3;
            int seg = (u & 7) * 4;
            cp16(so + (uint32_t)((row * SSTRIDE + seg) * 4),
                 At + (size_t)row * K + kc * 32 + seg);
            cp16(so + (uint32_t)((TILEF + row * SSTRIDE + seg) * 4),
                 Bt + (size_t)row * K + kc * 32 + seg);
        }
        asm volatile("cp.async.commit_group;" ::: "memory");
    };

    float c[4][4][4];
#pragma unroll
    for (int mf = 0; mf < 4; mf++)
#pragma unroll
        for (int nf = 0; nf < 4; nf++)
#pragma unroll
            for (int q = 0; q < 4; q++) c[mf][nf][q] = 0.0f;

    load_stage(0, 0);
    load_stage(1, 1);

    for (int s = 0; s < nk; ++s) {
        if (s + 2 < nk) {
            load_stage((s + 2) % 3, s + 2);
            asm volatile("cp.async.wait_group 2;" ::: "memory");
        } else if (s + 1 < nk) {
            asm volatile("cp.async.wait_group 1;" ::: "memory");
        } else {
            asm volatile("cp.async.wait_group 0;" ::: "memory");
        }
        __syncthreads();

        const float* As = smf + (s % 3) * STAGEF;
        const float* Bs = As + TILEF;

#pragma unroll
        for (int kk = 0; kk < 4; kk++) {
            const int kb = kk * 8;
            uint32_t ah[4][4], al[4][4], bh[4][2], bl[4][2];
#pragma unroll
            for (int mf = 0; mf < 4; mf++) {
                const int r0 = wm * 64 + mf * 16 + tr;
                float a0 = As[r0 * SSTRIDE + kb + tc];
                float a1 = As[(r0 + 8) * SSTRIDE + kb + tc];
                float a2 = As[r0 * SSTRIDE + kb + tc + 4];
                float a3 = As[(r0 + 8) * SSTRIDE + kb + tc + 4];
                if (PASSES == 3) {
                    tf32_split(a0, ah[mf][0], al[mf][0]);
                    tf32_split(a1, ah[mf][1], al[mf][1]);
                    tf32_split(a2, ah[mf][2], al[mf][2]);
                    tf32_split(a3, ah[mf][3], al[mf][3]);
                } else {
                    ah[mf][0] = tf32_hi(a0); ah[mf][1] = tf32_hi(a1);
                    ah[mf][2] = tf32_hi(a2); ah[mf][3] = tf32_hi(a3);
                }
            }
#pragma unroll
            for (int nf = 0; nf < 4; nf++) {
                const int n0 = wn * 32 + nf * 8 + tr;
                float b0 = Bs[n0 * SSTRIDE + kb + tc];
                float b1 = Bs[n0 * SSTRIDE + kb + tc + 4];
                if (PASSES == 3) {
                    tf32_split(b0, bh[nf][0], bl[nf][0]);
                    tf32_split(b1, bh[nf][1], bl[nf][1]);
                } else {
                    bh[nf][0] = tf32_hi(b0); bh[nf][1] = tf32_hi(b1);
                }
            }
#pragma unroll
            for (int mf = 0; mf < 4; mf++)
#pragma unroll
                for (int nf = 0; nf < 4; nf++) {
                    mma8(c[mf][nf], ah[mf][0], ah[mf][1], ah[mf][2], ah[mf][3],
                         bh[nf][0], bh[nf][1]);
                    if (PASSES == 3) {
                        mma8(c[mf][nf], ah[mf][0], ah[mf][1], ah[mf][2], ah[mf][3],
                             bl[nf][0], bl[nf][1]);
                        mma8(c[mf][nf], al[mf][0], al[mf][1], al[mf][2], al[mf][3],
                             bh[nf][0], bh[nf][1]);
                    }
                }
        }
        __syncthreads();   // protect stage buffer reuse
    }

    // --- epilogue ---
#pragma unroll
    for (int mf = 0; mf < 4; mf++) {
        const int r0g = bm + wm * 64 + mf * 16 + tr;
        const float rs0 = ROWSCALE ? rowscale[r0g] : 1.0f;
        const float rs1 = ROWSCALE ? rowscale[r0g + 8] : 1.0f;
#pragma unroll
        for (int nf = 0; nf < 4; nf++) {
            const int cg = bn + wn * 32 + nf * 8 + 2 * tc;
            float v0 = c[mf][nf][0], v1 = c[mf][nf][1];
            float v2 = c[mf][nf][2], v3 = c[mf][nf][3];
            if (ROWSCALE) { v0 *= rs0; v1 *= rs0; v2 *= rs1; v3 *= rs1; }
            if (BIAS) {
                float bb0 = bias[cg], bb1 = bias[cg + 1];
                v0 += bb0; v1 += bb1; v2 += bb0; v3 += bb1;
            }
            if (RELU) {
                v0 = fmaxf(v0, 0.0f); v1 = fmaxf(v1, 0.0f);
                v2 = fmaxf(v2, 0.0f); v3 = fmaxf(v3, 0.0f);
            }
            *(float2*)&C[(size_t)r0g * Ntot + cg]       = make_float2(v0, v1);
            *(float2*)&C[(size_t)(r0g + 8) * Ntot + cg] = make_float2(v2, v3);
        }
    }
}

// ============================================================================
// Elementwise / reduction kernels
// ============================================================================
__device__ __forceinline__ float warp_sum(float v) {
#pragma unroll
    for (int o = 16; o > 0; o >>= 1) v += __shfl_xor_sync(0xffffffffu, v, o);
    return v;
}
__device__ __forceinline__ float warp_max(float v) {
#pragma unroll
    for (int o = 16; o > 0; o >>= 1) v = fmaxf(v, __shfl_xor_sync(0xffffffffu, v, o));
    return v;
}

// 1/max(||x_row||,eps), warp per row (row = 1024 floats)
__global__ __launch_bounds__(256) void rowinv_kernel(const float* __restrict__ x) {
    const int row  = blockIdx.x * 8 + (threadIdx.x >> 5);
    const int lane = threadIdx.x & 31;
    const float4* p = (const float4*)(x + (size_t)row * SPATIAL);
    float s = 0.0f;
#pragma unroll
    for (int i = 0; i < 8; i++) {
        float4 v = p[lane + 32 * i];
        s += v.x * v.x + v.y * v.y + v.z * v.z + v.w * v.w;
    }
    s = warp_sum(s);
    if (lane == 0) g_invnorm[row] = 1.0f / fmaxf(sqrtf(s), 1e-12f);
}

// L2-normalize rows of g_memproc -> dst
__global__ __launch_bounds__(256) void rownorm_kernel(float* __restrict__ dst) {
    __shared__ float sm[8];
    const int row  = blockIdx.x;
    const int lane = threadIdx.x & 31;
    const int w    = threadIdx.x >> 5;
    const float4* p = (const float4*)(g_memproc + (size_t)row * SPATIAL);
    float4 v = p[threadIdx.x];
    float s = v.x * v.x + v.y * v.y + v.z * v.z + v.w * v.w;
    s = warp_sum(s);
    if (lane == 0) sm[w] = s;
    __syncthreads();
    float tot = 0.0f;
#pragma unroll
    for (int i = 0; i < 8; i++) tot += sm[i];
    float sc = 1.0f / fmaxf(sqrtf(tot), 1e-12f);
    float4 o = make_float4(v.x * sc, v.y * sc, v.z * sc, v.w * sc);
    ((float4*)(dst + (size_t)row * SPATIAL))[threadIdx.x] = o;
}

// transpose src [512,1024] -> g_mnT [1024,512]
__global__ __launch_bounds__(256) void transpose_kernel(const float* __restrict__ src) {
    __shared__ float t[32][33];
    const int bx = blockIdx.x * 32;   // src col base
    const int by = blockIdx.y * 32;   // src row base
    const int x = threadIdx.x & 31;
    const int y = threadIdx.x >> 5;   // 0..7
#pragma unroll
    for (int i = 0; i < 32; i += 8)
        t[y + i][x] = src[(size_t)(by + y + i) * SPATIAL + bx + x];
    __syncthreads();
#pragma unroll
    for (int i = 0; i < 32; i += 8)
        g_mnT[(size_t)(bx + y + i) * MDIM + by + x] = t[x][y + i];
}

// softmax over 512 cols, hard shrink, L1 renorm; warp per row, in place
__global__ __launch_bounds__(256) void softmax_shrink_kernel(float* __restrict__ S) {
    const int row  = blockIdx.x * 8 + (threadIdx.x >> 5);
    const int lane = threadIdx.x & 31;
    float4* p = (float4*)(S + (size_t)row * MDIM);
    float4 v[4];
#pragma unroll
    for (int i = 0; i < 4; i++) v[i] = p[lane + 32 * i];
    float m = -INFINITY;
#pragma unroll
    for (int i = 0; i < 4; i++)
        m = fmaxf(m, fmaxf(fmaxf(v[i].x, v[i].y), fmaxf(v[i].z, v[i].w)));
    m = warp_max(m);
    float s = 0.0f;
#pragma unroll
    for (int i = 0; i < 4; i++) {
        v[i].x = expf(v[i].x - m); v[i].y = expf(v[i].y - m);
        v[i].z = expf(v[i].z - m); v[i].w = expf(v[i].w - m);
        s += v[i].x + v[i].y + v[i].z + v[i].w;
    }
    s = warp_sum(s);
    const float inv = 1.0f / s;
    float t = 0.0f;
#pragma unroll
    for (int i = 0; i < 4; i++) {
        v[i].x = fmaxf(v[i].x * inv - 0.0025f, 0.0f);
        v[i].y = fmaxf(v[i].y * inv - 0.0025f, 0.0f);
        v[i].z = fmaxf(v[i].z * inv - 0.0025f, 0.0f);
        v[i].w = fmaxf(v[i].w * inv - 0.0025f, 0.0f);
        t += v[i].x + v[i].y + v[i].z + v[i].w;
    }
    t = warp_sum(t);
    const float inv2 = 1.0f / fmaxf(t, 1e-12f);
#pragma unroll
    for (int i = 0; i < 4; i++) {
        v[i].x *= inv2; v[i].y *= inv2; v[i].z *= inv2; v[i].w *= inv2;
        p[lane + 32 * i] = v[i];
    }
}

// att_channel_avg[n,m] = mean_c att[n*512+c, m]
__global__ __launch_bounds__(128) void chanmean_kernel(const float* __restrict__ att) {
    const int n = blockIdx.x;
    const int m = blockIdx.y * 128 + threadIdx.x;
    const float* base = att + ((size_t)n * 512) * MDIM + m;
    float s = 0.0f;
#pragma unroll 8
    for (int c = 0; c < 512; c++) s += base[(size_t)c * MDIM];
    g_avg[n * MDIM + m] = s * (1.0f / 512.0f);
}

// att_spatial broadcast
__global__ __launch_bounds__(256) void bcast_kernel(float* __restrict__ dst) {
    const int nm = blockIdx.x;
    const float v = g_avg[nm];
    float4 o = make_float4(v, v, v, v);
    ((float4*)(dst + (size_t)nm * SPATIAL))[threadIdx.x] = o;
}

// ============================================================================
extern "C" void kernel_launch(void* const* d_in, const int* in_sizes, int n_in,
                              void* d_out, int out_size) {
    (void)in_sizes; (void)n_in; (void)out_size;
    const float* x      = (const float*)d_in[0];
    const float* memory = (const float*)d_in[1];
    const float* w1     = (const float*)d_in[2];
    const float* b1     = (const float*)d_in[3];
    const float* w2     = (const float*)d_in[4];
    const float* b2     = (const float*)d_in[5];

    float* out = (float*)d_out;
    float* out_output  = out + OFF_OUTPUT;
    float* out_attsp   = out + OFF_ATTSP;
    float* out_inflat  = out + OFF_INFLAT;
    float* out_memnorm = out + OFF_MEMNORM;
    float* out_att     = out + OFF_ATT;

    float *p_h, *p_mp, *p_mnT, *p_inv;
    cudaGetSymbolAddress((void**)&p_h,   g_h);
    cudaGetSymbolAddress((void**)&p_mp,  g_memproc);
    cudaGetSymbolAddress((void**)&p_mnT, g_mnT);
    cudaGetSymbolAddress((void**)&p_inv, g_invnorm);

    cudaFuncSetAttribute((const void*)gemm_tc<1, true,  true,  false>,
                         cudaFuncAttributeMaxDynamicSharedMemorySize, GEMM_SMEM_BYTES);
    cudaFuncSetAttribute((const void*)gemm_tc<1, false, false, true>,
                         cudaFuncAttributeMaxDynamicSharedMemorySize, GEMM_SMEM_BYTES);
    cudaFuncSetAttribute((const void*)gemm_tc<1, false, false, false>,
                         cudaFuncAttributeMaxDynamicSharedMemorySize, GEMM_SMEM_BYTES);

    // input_flat = x (pure copy)
    cudaMemcpyAsync(out_inflat, x, (size_t)R_ROWS * SPATIAL * sizeof(float),
                    cudaMemcpyDeviceToDevice);

    // per-row inverse L2 norm of x (independent)
    rowinv_kernel<<<R_ROWS / 8, 256>>>(x);

    // MLP: h = relu(memory @ w1^T + b1)   [512,512]
    gemm_tc<1, true, true, false><<<dim3(4, 4), 256, GEMM_SMEM_BYTES>>>(
        HIDDIM, SPATIAL, memory, w1, p_h, b1, nullptr);
    // mem_proc = relu(h @ w2^T + b2)      [512,1024]
    gemm_tc<1, true, true, false><<<dim3(8, 4), 256, GEMM_SMEM_BYTES>>>(
        SPATIAL, HIDDIM, p_h, w2, p_mp, b2, nullptr);

    // memory_norm -> d_out
    rownorm_kernel<<<MDIM, 256>>>(out_memnorm);
    // mnT = transpose(memory_norm)
    transpose_kernel<<<dim3(SPATIAL / 32, MDIM / 32), 256>>>(out_memnorm);

    // S = diag(invnorm) * (x @ memory_norm^T) -> att section  (plain tf32)
    gemm_tc<1, false, false, true><<<dim3(4, R_ROWS / 128), 256, GEMM_SMEM_BYTES>>>(
        MDIM, SPATIAL, x, out_memnorm, out_att, nullptr, p_inv);

    // softmax + shrink + L1 renorm, in place
    softmax_shrink_kernel<<<R_ROWS / 8, 256>>>(out_att);

    // output = att @ mnT^T  [16384,1024]  (plain tf32)
    gemm_tc<1, false, false, false><<<dim3(8, R_ROWS / 128), 256, GEMM_SMEM_BYTES>>>(
        SPATIAL, MDIM, out_att, p_mnT, out_output, nullptr, nullptr);

    // channel-mean of att + spatial broadcast
    chanmean_kernel<<<dim3(32, MDIM / 128), 128>>>(out_att);
    bcast_kernel<<<R_ROWS, 256>>>(out_attsp);
}

// round 5
// speedup vs baseline: 3.5041x; 1.1915x over previous
#include <cuda_runtime.h>
#include <cuda_fp16.h>
#include <cstdint>
#include <math.h>

// Problem constants
#define R_ROWS  16384   // N*C
#define SPATIAL 1024    // H*W
#define MDIM    512     // mem_dim
#define HIDDIM  512     // spatial/2

// d_out section offsets (floats)
#define OFF_OUTPUT   ((size_t)0)
#define OFF_ATTSP    ((size_t)16777216)
#define OFF_INFLAT   ((size_t)33554432)
#define OFF_MEMNORM  ((size_t)50331648)
#define OFF_ATT      ((size_t)50855936)

// Device scratch (allocation-free)
__device__ float  g_h[MDIM * HIDDIM];
__device__ float  g_memproc[MDIM * SPATIAL];
__device__ float  g_invnorm[R_ROWS];
__device__ float  g_avg[32 * MDIM];
__device__ __half g_xh[(size_t)R_ROWS * SPATIAL];    // fp16 x
__device__ __half g_mnh[MDIM * SPATIAL];             // fp16 memory_norm
__device__ __half g_mnTh[SPATIAL * MDIM];            // fp16 memory_norm^T
__device__ __half g_atth[(size_t)R_ROWS * MDIM];     // fp16 att

// ============================================================================
// mma.sync helpers (sm_80+ — works on base compute_103 target)
// ============================================================================
__device__ __forceinline__ void mma8_tf32(float* c, uint32_t a0, uint32_t a1,
                                          uint32_t a2, uint32_t a3,
                                          uint32_t b0, uint32_t b1) {
    asm volatile(
        "mma.sync.aligned.m16n8k8.row.col.f32.tf32.tf32.f32 "
        "{%0,%1,%2,%3}, {%4,%5,%6,%7}, {%8,%9}, {%0,%1,%2,%3};"
        : "+f"(c[0]), "+f"(c[1]), "+f"(c[2]), "+f"(c[3])
        : "r"(a0), "r"(a1), "r"(a2), "r"(a3), "r"(b0), "r"(b1));
}

__device__ __forceinline__ void mma16_f16(float* c, uint32_t a0, uint32_t a1,
                                          uint32_t a2, uint32_t a3,
                                          uint32_t b0, uint32_t b1) {
    asm volatile(
        "mma.sync.aligned.m16n8k16.row.col.f32.f16.f16.f32 "
        "{%0,%1,%2,%3}, {%4,%5,%6,%7}, {%8,%9}, {%0,%1,%2,%3};"
        : "+f"(c[0]), "+f"(c[1]), "+f"(c[2]), "+f"(c[3])
        : "r"(a0), "r"(a1), "r"(a2), "r"(a3), "r"(b0), "r"(b1));
}

__device__ __forceinline__ uint32_t tf32_hi(float x) {
    uint32_t h;
    asm("cvt.rna.tf32.f32 %0, %1;" : "=r"(h) : "f"(x));
    return h;
}

__device__ __forceinline__ void cp16(uint32_t dst, const void* src) {
    asm volatile("cp.async.cg.shared.global [%0], [%1], 16;" :: "r"(dst), "l"(src));
}

__device__ __forceinline__ uint32_t pack_half2(float a, float b) {
    __half2 h = __floats2half2_rn(a, b);
    return *reinterpret_cast<uint32_t*>(&h);
}

// ============================================================================
// tf32 NT GEMM (kept for the small MLP GEMMs): C = op(A @ B^T)
// CTA 128x128xBK32, 8 warps, 3-stage cp.async.
// ============================================================================
#define SSTRIDE 36
#define TILEF   (128 * SSTRIDE)
#define STAGEF  (2 * TILEF)
#define GEMM_SMEM_BYTES (3 * STAGEF * 4)

template <bool RELU, bool BIAS>
__global__ void __launch_bounds__(256, 1) gemm_tc(
    int Ntot, int K,
    const float* __restrict__ A, const float* __restrict__ B,
    float* __restrict__ C,
    const float* __restrict__ bias)
{
    extern __shared__ float smf[];
    const uint32_t sbase = (uint32_t)__cvta_generic_to_shared(smf);
    const int tid  = threadIdx.x;
    const int wid  = tid >> 5;
    const int lane = tid & 31;
    const int wm   = wid & 1;
    const int wn   = wid >> 1;
    const int tr   = lane >> 2;
    const int tc   = lane & 3;

    const int bm = blockIdx.y * 128;
    const int bn = blockIdx.x * 128;
    const float* At = A + (size_t)bm * K;
    const float* Bt = B + (size_t)bn * K;
    const int nk = K >> 5;

    auto load_stage = [&](int st, int kc) {
        const uint32_t so = sbase + (uint32_t)(st * STAGEF * 4);
#pragma unroll
        for (int i = 0; i < 4; i++) {
            int u = tid + i * 256;
            int row = u >> 3;
            int seg = (u & 7) * 4;
            cp16(so + (uint32_t)((row * SSTRIDE + seg) * 4),
                 At + (size_t)row * K + kc * 32 + seg);
            cp16(so + (uint32_t)((TILEF + row * SSTRIDE + seg) * 4),
                 Bt + (size_t)row * K + kc * 32 + seg);
        }
        asm volatile("cp.async.commit_group;" ::: "memory");
    };

    float c[4][4][4];
#pragma unroll
    for (int mf = 0; mf < 4; mf++)
#pragma unroll
        for (int nf = 0; nf < 4; nf++)
#pragma unroll
            for (int q = 0; q < 4; q++) c[mf][nf][q] = 0.0f;

    load_stage(0, 0);
    load_stage(1, 1);

    for (int s = 0; s < nk; ++s) {
        if (s + 2 < nk) {
            load_stage((s + 2) % 3, s + 2);
            asm volatile("cp.async.wait_group 2;" ::: "memory");
        } else if (s + 1 < nk) {
            asm volatile("cp.async.wait_group 1;" ::: "memory");
        } else {
            asm volatile("cp.async.wait_group 0;" ::: "memory");
        }
        __syncthreads();

        const float* As = smf + (s % 3) * STAGEF;
        const float* Bs = As + TILEF;

#pragma unroll
        for (int kk = 0; kk < 4; kk++) {
            const int kb = kk * 8;
            uint32_t ah[4][4], bh[4][2];
#pragma unroll
            for (int mf = 0; mf < 4; mf++) {
                const int r0 = wm * 64 + mf * 16 + tr;
                ah[mf][0] = tf32_hi(As[r0 * SSTRIDE + kb + tc]);
                ah[mf][1] = tf32_hi(As[(r0 + 8) * SSTRIDE + kb + tc]);
                ah[mf][2] = tf32_hi(As[r0 * SSTRIDE + kb + tc + 4]);
                ah[mf][3] = tf32_hi(As[(r0 + 8) * SSTRIDE + kb + tc + 4]);
            }
#pragma unroll
            for (int nf = 0; nf < 4; nf++) {
                const int n0 = wn * 32 + nf * 8 + tr;
                bh[nf][0] = tf32_hi(Bs[n0 * SSTRIDE + kb + tc]);
                bh[nf][1] = tf32_hi(Bs[n0 * SSTRIDE + kb + tc + 4]);
            }
#pragma unroll
            for (int mf = 0; mf < 4; mf++)
#pragma unroll
                for (int nf = 0; nf < 4; nf++)
                    mma8_tf32(c[mf][nf], ah[mf][0], ah[mf][1], ah[mf][2], ah[mf][3],
                              bh[nf][0], bh[nf][1]);
        }
        __syncthreads();
    }

#pragma unroll
    for (int mf = 0; mf < 4; mf++) {
        const int r0g = bm + wm * 64 + mf * 16 + tr;
#pragma unroll
        for (int nf = 0; nf < 4; nf++) {
            const int cg = bn + wn * 32 + nf * 8 + 2 * tc;
            float v0 = c[mf][nf][0], v1 = c[mf][nf][1];
            float v2 = c[mf][nf][2], v3 = c[mf][nf][3];
            if (BIAS) {
                float bb0 = bias[cg], bb1 = bias[cg + 1];
                v0 += bb0; v1 += bb1; v2 += bb0; v3 += bb1;
            }
            if (RELU) {
                v0 = fmaxf(v0, 0.0f); v1 = fmaxf(v1, 0.0f);
                v2 = fmaxf(v2, 0.0f); v3 = fmaxf(v3, 0.0f);
            }
            *(float2*)&C[(size_t)r0g * Ntot + cg]       = make_float2(v0, v1);
            *(float2*)&C[(size_t)(r0g + 8) * Ntot + cg] = make_float2(v2, v3);
        }
    }
}

// ============================================================================
// fp16 NT GEMM: C[M,Ntot] = op( A[M,K] @ B[Ntot,K]^T ), fp32 accumulate.
// CTA 128x128xBK32(halfs), 8 warps (warp 64x32), 3-stage cp.async.
// Smem rows: 16 words (32 halfs) + 4 pad = stride 20 words (conflict-free).
// ============================================================================
#define SSW      20                          // word stride per 32-half row
#define HTILEW   (128 * SSW)                 // 2560 words per tile
#define HSTAGEW  (2 * HTILEW)
#define HGEMM_SMEM_BYTES (3 * HSTAGEW * 4)   // 61440 B

template <bool ROWSCALE>
__global__ void __launch_bounds__(256, 1) gemm_fp16(
    int Ntot, int K,        // K in halfs (multiple of 32)
    const __half* __restrict__ A, const __half* __restrict__ B,
    float* __restrict__ C,
    const float* __restrict__ rowscale)
{
    extern __shared__ uint32_t smw[];
    const uint32_t sbase = (uint32_t)__cvta_generic_to_shared(smw);
    const int tid  = threadIdx.x;
    const int wid  = tid >> 5;
    const int lane = tid & 31;
    const int wm   = wid & 1;
    const int wn   = wid >> 1;
    const int tr   = lane >> 2;
    const int tc   = lane & 3;

    const int bm = blockIdx.y * 128;
    const int bn = blockIdx.x * 128;
    const __half* At = A + (size_t)bm * K;
    const __half* Bt = B + (size_t)bn * K;
    const int nk = K >> 5;

    auto load_stage = [&](int st, int kc) {
        const uint32_t so = sbase + (uint32_t)(st * HSTAGEW * 4);
#pragma unroll
        for (int i = 0; i < 2; i++) {
            int u = tid + i * 256;           // 0..511
            int row = u >> 2;                // 0..127
            int seg = (u & 3) * 4;           // word seg 0,4,8,12
            cp16(so + (uint32_t)((row * SSW + seg) * 4),
                 At + (size_t)row * K + kc * 32 + seg * 2);
            cp16(so + (uint32_t)((HTILEW + row * SSW + seg) * 4),
                 Bt + (size_t)row * K + kc * 32 + seg * 2);
        }
        asm volatile("cp.async.commit_group;" ::: "memory");
    };

    float c[4][4][4];
#pragma unroll
    for (int mf = 0; mf < 4; mf++)
#pragma unroll
        for (int nf = 0; nf < 4; nf++)
#pragma unroll
            for (int q = 0; q < 4; q++) c[mf][nf][q] = 0.0f;

    load_stage(0, 0);
    load_stage(1, 1);

    for (int s = 0; s < nk; ++s) {
        if (s + 2 < nk) {
            load_stage((s + 2) % 3, s + 2);
            asm volatile("cp.async.wait_group 2;" ::: "memory");
        } else if (s + 1 < nk) {
            asm volatile("cp.async.wait_group 1;" ::: "memory");
        } else {
            asm volatile("cp.async.wait_group 0;" ::: "memory");
        }
        __syncthreads();

        const uint32_t* As = smw + (s % 3) * HSTAGEW;
        const uint32_t* Bs = As + HTILEW;

#pragma unroll
        for (int kk = 0; kk < 2; kk++) {          // two k16 slabs per 32-half chunk
            const int kb = kk * 8;                // word offset
            uint32_t a[4][4], b[4][2];
#pragma unroll
            for (int mf = 0; mf < 4; mf++) {
                const int r0 = wm * 64 + mf * 16 + tr;
                a[mf][0] = As[r0 * SSW + kb + tc];
                a[mf][1] = As[(r0 + 8) * SSW + kb + tc];
                a[mf][2] = As[r0 * SSW + kb + tc + 4];
                a[mf][3] = As[(r0 + 8) * SSW + kb + tc + 4];
            }
#pragma unroll
            for (int nf = 0; nf < 4; nf++) {
                const int n0 = wn * 32 + nf * 8 + tr;
                b[nf][0] = Bs[n0 * SSW + kb + tc];
                b[nf][1] = Bs[n0 * SSW + kb + tc + 4];
            }
#pragma unroll
            for (int mf = 0; mf < 4; mf++)
#pragma unroll
                for (int nf = 0; nf < 4; nf++)
                    mma16_f16(c[mf][nf], a[mf][0], a[mf][1], a[mf][2], a[mf][3],
                              b[nf][0], b[nf][1]);
        }
        __syncthreads();
    }

#pragma unroll
    for (int mf = 0; mf < 4; mf++) {
        const int r0g = bm + wm * 64 + mf * 16 + tr;
        const float rs0 = ROWSCALE ? rowscale[r0g] : 1.0f;
        const float rs1 = ROWSCALE ? rowscale[r0g + 8] : 1.0f;
#pragma unroll
        for (int nf = 0; nf < 4; nf++) {
            const int cg = bn + wn * 32 + nf * 8 + 2 * tc;
            float v0 = c[mf][nf][0], v1 = c[mf][nf][1];
            float v2 = c[mf][nf][2], v3 = c[mf][nf][3];
            if (ROWSCALE) { v0 *= rs0; v1 *= rs0; v2 *= rs1; v3 *= rs1; }
            *(float2*)&C[(size_t)r0g * Ntot + cg]       = make_float2(v0, v1);
            *(float2*)&C[(size_t)(r0g + 8) * Ntot + cg] = make_float2(v2, v3);
        }
    }
}

// ============================================================================
// Elementwise / reduction kernels
// ============================================================================
__device__ __forceinline__ float warp_sum(float v) {
#pragma unroll
    for (int o = 16; o > 0; o >>= 1) v += __shfl_xor_sync(0xffffffffu, v, o);
    return v;
}
__device__ __forceinline__ float warp_max(float v) {
#pragma unroll
    for (int o = 16; o > 0; o >>= 1) v = fmaxf(v, __shfl_xor_sync(0xffffffffu, v, o));
    return v;
}

// 1/max(||x_row||,eps)  AND  fp16 copy of x. Warp per row.
__global__ __launch_bounds__(256) void rowinv_cvt_kernel(const float* __restrict__ x) {
    const int row  = blockIdx.x * 8 + (threadIdx.x >> 5);
    const int lane = threadIdx.x & 31;
    const float4* p = (const float4*)(x + (size_t)row * SPATIAL);
    uint2* xo = (uint2*)(g_xh + (size_t)row * SPATIAL);
    float s = 0.0f;
#pragma unroll
    for (int i = 0; i < 8; i++) {
        float4 v = p[lane + 32 * i];
        s += v.x * v.x + v.y * v.y + v.z * v.z + v.w * v.w;
        xo[lane + 32 * i] = make_uint2(pack_half2(v.x, v.y), pack_half2(v.z, v.w));
    }
    s = warp_sum(s);
    if (lane == 0) g_invnorm[row] = 1.0f / fmaxf(sqrtf(s), 1e-12f);
}

// L2-normalize rows of g_memproc -> dst (f32)  AND  g_mnh (fp16)
__global__ __launch_bounds__(256) void rownorm_kernel(float* __restrict__ dst) {
    __shared__ float sm[8];
    const int row  = blockIdx.x;
    const int lane = threadIdx.x & 31;
    const int w    = threadIdx.x >> 5;
    const float4* p = (const float4*)(g_memproc + (size_t)row * SPATIAL);
    float4 v = p[threadIdx.x];
    float s = v.x * v.x + v.y * v.y + v.z * v.z + v.w * v.w;
    s = warp_sum(s);
    if (lane == 0) sm[w] = s;
    __syncthreads();
    float tot = 0.0f;
#pragma unroll
    for (int i = 0; i < 8; i++) tot += sm[i];
    float sc = 1.0f / fmaxf(sqrtf(tot), 1e-12f);
    float4 o = make_float4(v.x * sc, v.y * sc, v.z * sc, v.w * sc);
    ((float4*)(dst + (size_t)row * SPATIAL))[threadIdx.x] = o;
    ((uint2*)(g_mnh + (size_t)row * SPATIAL))[threadIdx.x] =
        make_uint2(pack_half2(o.x, o.y), pack_half2(o.z, o.w));
}

// transpose f32 src [512,1024] -> fp16 g_mnTh [1024,512]
__global__ __launch_bounds__(256) void transpose_kernel(const float* __restrict__ src) {
    __shared__ float t[32][33];
    const int bx = blockIdx.x * 32;
    const int by = blockIdx.y * 32;
    const int x = threadIdx.x & 31;
    const int y = threadIdx.x >> 5;
#pragma unroll
    for (int i = 0; i < 32; i += 8)
        t[y + i][x] = src[(size_t)(by + y + i) * SPATIAL + bx + x];
    __syncthreads();
#pragma unroll
    for (int i = 0; i < 32; i += 8)
        g_mnTh[(size_t)(bx + y + i) * MDIM + by + x] = __float2half_rn(t[x][y + i]);
}

// softmax + shrink + L1 renorm, in place (f32)  AND fp16 copy. Warp per row.
__global__ __launch_bounds__(256) void softmax_shrink_kernel(float* __restrict__ S) {
    const int row  = blockIdx.x * 8 + (threadIdx.x >> 5);
    const int lane = threadIdx.x & 31;
    float4* p = (float4*)(S + (size_t)row * MDIM);
    uint2* ph = (uint2*)(g_atth + (size_t)row * MDIM);
    float4 v[4];
#pragma unroll
    for (int i = 0; i < 4; i++) v[i] = p[lane + 32 * i];
    float m = -INFINITY;
#pragma unroll
    for (int i = 0; i < 4; i++)
        m = fmaxf(m, fmaxf(fmaxf(v[i].x, v[i].y), fmaxf(v[i].z, v[i].w)));
    m = warp_max(m);
    float s = 0.0f;
#pragma unroll
    for (int i = 0; i < 4; i++) {
        v[i].x = expf(v[i].x - m); v[i].y = expf(v[i].y - m);
        v[i].z = expf(v[i].z - m); v[i].w = expf(v[i].w - m);
        s += v[i].x + v[i].y + v[i].z + v[i].w;
    }
    s = warp_sum(s);
    const float inv = 1.0f / s;
    float t = 0.0f;
#pragma unroll
    for (int i = 0; i < 4; i++) {
        v[i].x = fmaxf(v[i].x * inv - 0.0025f, 0.0f);
        v[i].y = fmaxf(v[i].y * inv - 0.0025f, 0.0f);
        v[i].z = fmaxf(v[i].z * inv - 0.0025f, 0.0f);
        v[i].w = fmaxf(v[i].w * inv - 0.0025f, 0.0f);
        t += v[i].x + v[i].y + v[i].z + v[i].w;
    }
    t = warp_sum(t);
    const float inv2 = 1.0f / fmaxf(t, 1e-12f);
#pragma unroll
    for (int i = 0; i < 4; i++) {
        v[i].x *= inv2; v[i].y *= inv2; v[i].z *= inv2; v[i].w *= inv2;
        p[lane + 32 * i] = v[i];
        ph[lane + 32 * i] = make_uint2(pack_half2(v[i].x, v[i].y),
                                       pack_half2(v[i].z, v[i].w));
    }
}

// att_channel_avg[n,m] = mean_c att[n*512+c, m]
__global__ __launch_bounds__(128) void chanmean_kernel(const float* __restrict__ att) {
    const int n = blockIdx.x;
    const int m = blockIdx.y * 128 + threadIdx.x;
    const float* base = att + ((size_t)n * 512) * MDIM + m;
    float s = 0.0f;
#pragma unroll 8
    for (int c = 0; c < 512; c++) s += base[(size_t)c * MDIM];
    g_avg[n * MDIM + m] = s * (1.0f / 512.0f);
}

// att_spatial broadcast
__global__ __launch_bounds__(256) void bcast_kernel(float* __restrict__ dst) {
    const int nm = blockIdx.x;
    const float v = g_avg[nm];
    float4 o = make_float4(v, v, v, v);
    ((float4*)(dst + (size_t)nm * SPATIAL))[threadIdx.x] = o;
}

// ============================================================================
extern "C" void kernel_launch(void* const* d_in, const int* in_sizes, int n_in,
                              void* d_out, int out_size) {
    (void)in_sizes; (void)n_in; (void)out_size;
    const float* x      = (const float*)d_in[0];
    const float* memory = (const float*)d_in[1];
    const float* w1     = (const float*)d_in[2];
    const float* b1     = (const float*)d_in[3];
    const float* w2     = (const float*)d_in[4];
    const float* b2     = (const float*)d_in[5];

    float* out = (float*)d_out;
    float* out_output  = out + OFF_OUTPUT;
    float* out_attsp   = out + OFF_ATTSP;
    float* out_inflat  = out + OFF_INFLAT;
    float* out_memnorm = out + OFF_MEMNORM;
    float* out_att     = out + OFF_ATT;

    float *p_h, *p_mp, *p_inv;
    __half *p_xh, *p_mnh, *p_mnTh, *p_atth;
    cudaGetSymbolAddress((void**)&p_h,    g_h);
    cudaGetSymbolAddress((void**)&p_mp,   g_memproc);
    cudaGetSymbolAddress((void**)&p_inv,  g_invnorm);
    cudaGetSymbolAddress((void**)&p_xh,   g_xh);
    cudaGetSymbolAddress((void**)&p_mnh,  g_mnh);
    cudaGetSymbolAddress((void**)&p_mnTh, g_mnTh);
    cudaGetSymbolAddress((void**)&p_atth, g_atth);

    cudaFuncSetAttribute((const void*)gemm_tc<true, true>,
                         cudaFuncAttributeMaxDynamicSharedMemorySize, GEMM_SMEM_BYTES);
    cudaFuncSetAttribute((const void*)gemm_fp16<true>,
                         cudaFuncAttributeMaxDynamicSharedMemorySize, HGEMM_SMEM_BYTES);
    cudaFuncSetAttribute((const void*)gemm_fp16<false>,
                         cudaFuncAttributeMaxDynamicSharedMemorySize, HGEMM_SMEM_BYTES);

    // input_flat = x (pure copy)
    cudaMemcpyAsync(out_inflat, x, (size_t)R_ROWS * SPATIAL * sizeof(float),
                    cudaMemcpyDeviceToDevice);

    // inverse L2 norms of x rows + fp16 conversion of x
    rowinv_cvt_kernel<<<R_ROWS / 8, 256>>>(x);

    // MLP: h = relu(memory @ w1^T + b1)   [512,512]  (tf32)
    gemm_tc<true, true><<<dim3(4, 4), 256, GEMM_SMEM_BYTES>>>(
        HIDDIM, SPATIAL, memory, w1, p_h, b1);
    // mem_proc = relu(h @ w2^T + b2)      [512,1024] (tf32)
    gemm_tc<true, true><<<dim3(8, 4), 256, GEMM_SMEM_BYTES>>>(
        SPATIAL, HIDDIM, p_h, w2, p_mp, b2);

    // memory_norm -> d_out (f32) + g_mnh (fp16)
    rownorm_kernel<<<MDIM, 256>>>(out_memnorm);
    // mnT (fp16) = transpose(memory_norm)
    transpose_kernel<<<dim3(SPATIAL / 32, MDIM / 32), 256>>>(out_memnorm);

    // S = diag(invnorm) * (x_h @ mn_h^T) -> att section (fp16 MMA, f32 accum)
    gemm_fp16<true><<<dim3(4, R_ROWS / 128), 256, HGEMM_SMEM_BYTES>>>(
        MDIM, SPATIAL, p_xh, p_mnh, out_att, p_inv);

    // softmax + shrink + L1 renorm (f32 in place) + fp16 copy
    softmax_shrink_kernel<<<R_ROWS / 8, 256>>>(out_att);

    // output = att_h @ mnT_h^T  [16384,1024]
    gemm_fp16<false><<<dim3(8, R_ROWS / 128), 256, HGEMM_SMEM_BYTES>>>(
        SPATIAL, MDIM, p_atth, p_mnTh, out_output, nullptr);

    // channel-mean of att + spatial broadcast
    chanmean_kernel<<<dim3(32, MDIM / 128), 128>>>(out_att);
    bcast_kernel<<<R_ROWS, 256>>>(out_attsp);
}

// round 6
// speedup vs baseline: 3.5465x; 1.0121x over previous
#include <cuda_runtime.h>
#include <cuda_fp16.h>
#include <cstdint>
#include <math.h>

// Problem constants
#define R_ROWS  16384   // N*C
#define SPATIAL 1024    // H*W
#define MDIM    512     // mem_dim
#define HIDDIM  512     // spatial/2

// d_out section offsets (floats)
#define OFF_OUTPUT   ((size_t)0)
#define OFF_ATTSP    ((size_t)16777216)
#define OFF_INFLAT   ((size_t)33554432)
#define OFF_MEMNORM  ((size_t)50331648)
#define OFF_ATT      ((size_t)50855936)

// Device scratch (allocation-free)
__device__ float  g_h[MDIM * HIDDIM];
__device__ float  g_memproc[MDIM * SPATIAL];
__device__ float  g_invnorm[R_ROWS];
__device__ float  g_avg[32 * MDIM];
__device__ __half g_xh[(size_t)R_ROWS * SPATIAL];    // fp16 x
__device__ __half g_mnh[MDIM * SPATIAL];             // fp16 memory_norm
__device__ __half g_mnTh[SPATIAL * MDIM];            // fp16 memory_norm^T
__device__ __half g_atth[(size_t)R_ROWS * MDIM];     // fp16 att

// ============================================================================
// mma.sync helpers (sm_80+ — works on base compute_103 target)
// ============================================================================
__device__ __forceinline__ void mma8_tf32(float* c, uint32_t a0, uint32_t a1,
                                          uint32_t a2, uint32_t a3,
                                          uint32_t b0, uint32_t b1) {
    asm volatile(
        "mma.sync.aligned.m16n8k8.row.col.f32.tf32.tf32.f32 "
        "{%0,%1,%2,%3}, {%4,%5,%6,%7}, {%8,%9}, {%0,%1,%2,%3};"
        : "+f"(c[0]), "+f"(c[1]), "+f"(c[2]), "+f"(c[3])
        : "r"(a0), "r"(a1), "r"(a2), "r"(a3), "r"(b0), "r"(b1));
}

__device__ __forceinline__ void mma16_f16(float* c, uint32_t a0, uint32_t a1,
                                          uint32_t a2, uint32_t a3,
                                          uint32_t b0, uint32_t b1) {
    asm volatile(
        "mma.sync.aligned.m16n8k16.row.col.f32.f16.f16.f32 "
        "{%0,%1,%2,%3}, {%4,%5,%6,%7}, {%8,%9}, {%0,%1,%2,%3};"
        : "+f"(c[0]), "+f"(c[1]), "+f"(c[2]), "+f"(c[3])
        : "r"(a0), "r"(a1), "r"(a2), "r"(a3), "r"(b0), "r"(b1));
}

__device__ __forceinline__ void ldmx4(uint32_t& r0, uint32_t& r1,
                                      uint32_t& r2, uint32_t& r3, uint32_t addr) {
    asm volatile("ldmatrix.sync.aligned.m8n8.x4.shared.b16 {%0,%1,%2,%3}, [%4];"
                 : "=r"(r0), "=r"(r1), "=r"(r2), "=r"(r3) : "r"(addr));
}

__device__ __forceinline__ uint32_t tf32_hi(float x) {
    uint32_t h;
    asm("cvt.rna.tf32.f32 %0, %1;" : "=r"(h) : "f"(x));
    return h;
}

__device__ __forceinline__ void cp16(uint32_t dst, const void* src) {
    asm volatile("cp.async.cg.shared.global [%0], [%1], 16;" :: "r"(dst), "l"(src));
}

__device__ __forceinline__ uint32_t pack_half2(float a, float b) {
    __half2 h = __floats2half2_rn(a, b);
    return *reinterpret_cast<uint32_t*>(&h);
}

// ============================================================================
// tf32 NT GEMM (small MLP GEMMs — precision-critical, keep tf32)
// CTA 128x128xBK32, 8 warps, 3-stage cp.async.
// ============================================================================
#define SSTRIDE 36
#define TILEF   (128 * SSTRIDE)
#define STAGEF  (2 * TILEF)
#define GEMM_SMEM_BYTES (3 * STAGEF * 4)

template <bool RELU, bool BIAS>
__global__ void __launch_bounds__(256, 1) gemm_tc(
    int Ntot, int K,
    const float* __restrict__ A, const float* __restrict__ B,
    float* __restrict__ C,
    const float* __restrict__ bias)
{
    extern __shared__ float smf[];
    const uint32_t sbase = (uint32_t)__cvta_generic_to_shared(smf);
    const int tid  = threadIdx.x;
    const int wid  = tid >> 5;
    const int lane = tid & 31;
    const int wm   = wid & 1;
    const int wn   = wid >> 1;
    const int tr   = lane >> 2;
    const int tc   = lane & 3;

    const int bm = blockIdx.y * 128;
    const int bn = blockIdx.x * 128;
    const float* At = A + (size_t)bm * K;
    const float* Bt = B + (size_t)bn * K;
    const int nk = K >> 5;

    auto load_stage = [&](int st, int kc) {
        const uint32_t so = sbase + (uint32_t)(st * STAGEF * 4);
#pragma unroll
        for (int i = 0; i < 4; i++) {
            int u = tid + i * 256;
            int row = u >> 3;
            int seg = (u & 7) * 4;
            cp16(so + (uint32_t)((row * SSTRIDE + seg) * 4),
                 At + (size_t)row * K + kc * 32 + seg);
            cp16(so + (uint32_t)((TILEF + row * SSTRIDE + seg) * 4),
                 Bt + (size_t)row * K + kc * 32 + seg);
        }
        asm volatile("cp.async.commit_group;" ::: "memory");
    };

    float c[4][4][4];
#pragma unroll
    for (int mf = 0; mf < 4; mf++)
#pragma unroll
        for (int nf = 0; nf < 4; nf++)
#pragma unroll
            for (int q = 0; q < 4; q++) c[mf][nf][q] = 0.0f;

    load_stage(0, 0);
    load_stage(1, 1);

    for (int s = 0; s < nk; ++s) {
        if (s + 2 < nk) {
            load_stage((s + 2) % 3, s + 2);
            asm volatile("cp.async.wait_group 2;" ::: "memory");
        } else if (s + 1 < nk) {
            asm volatile("cp.async.wait_group 1;" ::: "memory");
        } else {
            asm volatile("cp.async.wait_group 0;" ::: "memory");
        }
        __syncthreads();

        const float* As = smf + (s % 3) * STAGEF;
        const float* Bs = As + TILEF;

#pragma unroll
        for (int kk = 0; kk < 4; kk++) {
            const int kb = kk * 8;
            uint32_t ah[4][4], bh[4][2];
#pragma unroll
            for (int mf = 0; mf < 4; mf++) {
                const int r0 = wm * 64 + mf * 16 + tr;
                ah[mf][0] = tf32_hi(As[r0 * SSTRIDE + kb + tc]);
                ah[mf][1] = tf32_hi(As[(r0 + 8) * SSTRIDE + kb + tc]);
                ah[mf][2] = tf32_hi(As[r0 * SSTRIDE + kb + tc + 4]);
                ah[mf][3] = tf32_hi(As[(r0 + 8) * SSTRIDE + kb + tc + 4]);
            }
#pragma unroll
            for (int nf = 0; nf < 4; nf++) {
                const int n0 = wn * 32 + nf * 8 + tr;
                bh[nf][0] = tf32_hi(Bs[n0 * SSTRIDE + kb + tc]);
                bh[nf][1] = tf32_hi(Bs[n0 * SSTRIDE + kb + tc + 4]);
            }
#pragma unroll
            for (int mf = 0; mf < 4; mf++)
#pragma unroll
                for (int nf = 0; nf < 4; nf++)
                    mma8_tf32(c[mf][nf], ah[mf][0], ah[mf][1], ah[mf][2], ah[mf][3],
                              bh[nf][0], bh[nf][1]);
        }
        __syncthreads();
    }

#pragma unroll
    for (int mf = 0; mf < 4; mf++) {
        const int r0g = bm + wm * 64 + mf * 16 + tr;
#pragma unroll
        for (int nf = 0; nf < 4; nf++) {
            const int cg = bn + wn * 32 + nf * 8 + 2 * tc;
            float v0 = c[mf][nf][0], v1 = c[mf][nf][1];
            float v2 = c[mf][nf][2], v3 = c[mf][nf][3];
            if (BIAS) {
                float bb0 = bias[cg], bb1 = bias[cg + 1];
                v0 += bb0; v1 += bb1; v2 += bb0; v3 += bb1;
            }
            if (RELU) {
                v0 = fmaxf(v0, 0.0f); v1 = fmaxf(v1, 0.0f);
                v2 = fmaxf(v2, 0.0f); v3 = fmaxf(v3, 0.0f);
            }
            *(float2*)&C[(size_t)r0g * Ntot + cg]       = make_float2(v0, v1);
            *(float2*)&C[(size_t)(r0g + 8) * Ntot + cg] = make_float2(v2, v3);
        }
    }
}

// ============================================================================
// fp16 NT GEMM with ldmatrix fragment loads.
// C[M,Ntot] = op( A[M,K] @ B[Ntot,K]^T ), fp32 accumulate.
// CTA 128x128xBK32(halfs), 8 warps (warp 64x32), 3-stage cp.async.
// Smem rows: 16 words (32 halfs) + 4 pad = stride 20 words.
// ============================================================================
#define SSW      20
#define HTILEW   (128 * SSW)
#define HSTAGEW  (2 * HTILEW)
#define HGEMM_SMEM_BYTES (3 * HSTAGEW * 4)

template <bool ROWSCALE>
__global__ void __launch_bounds__(256, 1) gemm_fp16(
    int Ntot, int K,        // K in halfs (multiple of 32)
    const __half* __restrict__ A, const __half* __restrict__ B,
    float* __restrict__ C,
    const float* __restrict__ rowscale)
{
    extern __shared__ uint32_t smw[];
    const uint32_t sbase = (uint32_t)__cvta_generic_to_shared(smw);
    const int tid  = threadIdx.x;
    const int wid  = tid >> 5;
    const int lane = tid & 31;
    const int wm   = wid & 1;
    const int wn   = wid >> 1;
    const int tr   = lane >> 2;
    const int tc   = lane & 3;

    const int bm = blockIdx.y * 128;
    const int bn = blockIdx.x * 128;
    const __half* At = A + (size_t)bm * K;
    const __half* Bt = B + (size_t)bn * K;
    const int nk = K >> 5;

    // ldmatrix per-lane row/column bases (derived from scalar fragment layout)
    const int q = lane >> 3;                 // matrix index 0..3
    const int rsub = lane & 7;
    // A x4: matrices = {rows r0..r0+7, klo}, {r0+8.., klo}, {r0.., khi}, {r0+8.., khi}
    const int arow = wm * 64 + rsub + (q & 1) * 8;       // + mf*16
    const int acolw = (q >> 1) * 4;
    // B x4: matrices = {n0..n0+7, klo}, {n0.., khi}, {n0+8.., klo}, {n0+8.., khi}
    const int brow = wn * 32 + rsub + (q >> 1) * 8;      // + nf2*16
    const int bcolw = (q & 1) * 4;

    auto load_stage = [&](int st, int kc) {
        const uint32_t so = sbase + (uint32_t)(st * HSTAGEW * 4);
#pragma unroll
        for (int i = 0; i < 2; i++) {
            int u = tid + i * 256;
            int row = u >> 2;
            int seg = (u & 3) * 4;
            cp16(so + (uint32_t)((row * SSW + seg) * 4),
                 At + (size_t)row * K + kc * 32 + seg * 2);
            cp16(so + (uint32_t)((HTILEW + row * SSW + seg) * 4),
                 Bt + (size_t)row * K + kc * 32 + seg * 2);
        }
        asm volatile("cp.async.commit_group;" ::: "memory");
    };

    float c[4][4][4];
#pragma unroll
    for (int mf = 0; mf < 4; mf++)
#pragma unroll
        for (int nf = 0; nf < 4; nf++)
#pragma unroll
            for (int qq = 0; qq < 4; qq++) c[mf][nf][qq] = 0.0f;

    load_stage(0, 0);
    load_stage(1, 1);

    for (int s = 0; s < nk; ++s) {
        if (s + 2 < nk) {
            load_stage((s + 2) % 3, s + 2);
            asm volatile("cp.async.wait_group 2;" ::: "memory");
        } else if (s + 1 < nk) {
            asm volatile("cp.async.wait_group 1;" ::: "memory");
        } else {
            asm volatile("cp.async.wait_group 0;" ::: "memory");
        }
        __syncthreads();

        const uint32_t stage = sbase + (uint32_t)((s % 3) * HSTAGEW * 4);
        const uint32_t aAddr0 = stage + (uint32_t)((arow * SSW + acolw) * 4);
        const uint32_t bAddr0 = stage + (uint32_t)((HTILEW + brow * SSW + bcolw) * 4);

#pragma unroll
        for (int kk = 0; kk < 2; kk++) {
            const uint32_t kboff = (uint32_t)(kk * 8 * 4);
            uint32_t a[4][4], b[4][2];
#pragma unroll
            for (int mf = 0; mf < 4; mf++)
                ldmx4(a[mf][0], a[mf][1], a[mf][2], a[mf][3],
                      aAddr0 + kboff + (uint32_t)(mf * 16 * SSW * 4));
#pragma unroll
            for (int nf2 = 0; nf2 < 2; nf2++)
                ldmx4(b[2 * nf2][0], b[2 * nf2][1], b[2 * nf2 + 1][0], b[2 * nf2 + 1][1],
                      bAddr0 + kboff + (uint32_t)(nf2 * 16 * SSW * 4));
#pragma unroll
            for (int mf = 0; mf < 4; mf++)
#pragma unroll
                for (int nf = 0; nf < 4; nf++)
                    mma16_f16(c[mf][nf], a[mf][0], a[mf][1], a[mf][2], a[mf][3],
                              b[nf][0], b[nf][1]);
        }
        __syncthreads();
    }

#pragma unroll
    for (int mf = 0; mf < 4; mf++) {
        const int r0g = bm + wm * 64 + mf * 16 + tr;
        const float rs0 = ROWSCALE ? rowscale[r0g] : 1.0f;
        const float rs1 = ROWSCALE ? rowscale[r0g + 8] : 1.0f;
#pragma unroll
        for (int nf = 0; nf < 4; nf++) {
            const int cg = bn + wn * 32 + nf * 8 + 2 * tc;
            float v0 = c[mf][nf][0], v1 = c[mf][nf][1];
            float v2 = c[mf][nf][2], v3 = c[mf][nf][3];
            if (ROWSCALE) { v0 *= rs0; v1 *= rs0; v2 *= rs1; v3 *= rs1; }
            *(float2*)&C[(size_t)r0g * Ntot + cg]       = make_float2(v0, v1);
            *(float2*)&C[(size_t)(r0g + 8) * Ntot + cg] = make_float2(v2, v3);
        }
    }
}

// ============================================================================
// Elementwise / reduction kernels
// ============================================================================
__device__ __forceinline__ float warp_sum(float v) {
#pragma unroll
    for (int o = 16; o > 0; o >>= 1) v += __shfl_xor_sync(0xffffffffu, v, o);
    return v;
}
__device__ __forceinline__ float warp_max(float v) {
#pragma unroll
    for (int o = 16; o > 0; o >>= 1) v = fmaxf(v, __shfl_xor_sync(0xffffffffu, v, o));
    return v;
}

// 1/max(||x_row||,eps)  AND  fp16 copy of x. Warp per row.
__global__ __launch_bounds__(256) void rowinv_cvt_kernel(const float* __restrict__ x) {
    const int row  = blockIdx.x * 8 + (threadIdx.x >> 5);
    const int lane = threadIdx.x & 31;
    const float4* p = (const float4*)(x + (size_t)row * SPATIAL);
    uint2* xo = (uint2*)(g_xh + (size_t)row * SPATIAL);
    float s = 0.0f;
#pragma unroll
    for (int i = 0; i < 8; i++) {
        float4 v = p[lane + 32 * i];
        s += v.x * v.x + v.y * v.y + v.z * v.z + v.w * v.w;
        xo[lane + 32 * i] = make_uint2(pack_half2(v.x, v.y), pack_half2(v.z, v.w));
    }
    s = warp_sum(s);
    if (lane == 0) g_invnorm[row] = 1.0f / fmaxf(sqrtf(s), 1e-12f);
}

// L2-normalize rows of g_memproc -> dst (f32)  AND  g_mnh (fp16)
__global__ __launch_bounds__(256) void rownorm_kernel(float* __restrict__ dst) {
    __shared__ float sm[8];
    const int row  = blockIdx.x;
    const int lane = threadIdx.x & 31;
    const int w    = threadIdx.x >> 5;
    const float4* p = (const float4*)(g_memproc + (size_t)row * SPATIAL);
    float4 v = p[threadIdx.x];
    float s = v.x * v.x + v.y * v.y + v.z * v.z + v.w * v.w;
    s = warp_sum(s);
    if (lane == 0) sm[w] = s;
    __syncthreads();
    float tot = 0.0f;
#pragma unroll
    for (int i = 0; i < 8; i++) tot += sm[i];
    float sc = 1.0f / fmaxf(sqrtf(tot), 1e-12f);
    float4 o = make_float4(v.x * sc, v.y * sc, v.z * sc, v.w * sc);
    ((float4*)(dst + (size_t)row * SPATIAL))[threadIdx.x] = o;
    ((uint2*)(g_mnh + (size_t)row * SPATIAL))[threadIdx.x] =
        make_uint2(pack_half2(o.x, o.y), pack_half2(o.z, o.w));
}

// transpose f32 src [512,1024] -> fp16 g_mnTh [1024,512]
__global__ __launch_bounds__(256) void transpose_kernel(const float* __restrict__ src) {
    __shared__ float t[32][33];
    const int bx = blockIdx.x * 32;
    const int by = blockIdx.y * 32;
    const int x = threadIdx.x & 31;
    const int y = threadIdx.x >> 5;
#pragma unroll
    for (int i = 0; i < 32; i += 8)
        t[y + i][x] = src[(size_t)(by + y + i) * SPATIAL + bx + x];
    __syncthreads();
#pragma unroll
    for (int i = 0; i < 32; i += 8)
        g_mnTh[(size_t)(bx + y + i) * MDIM + by + x] = __float2half_rn(t[x][y + i]);
}

// softmax + shrink + L1 renorm, in place (f32)  AND fp16 copy. Warp per row.
__global__ __launch_bounds__(256) void softmax_shrink_kernel(float* __restrict__ S) {
    const int row  = blockIdx.x * 8 + (threadIdx.x >> 5);
    const int lane = threadIdx.x & 31;
    float4* p = (float4*)(S + (size_t)row * MDIM);
    uint2* ph = (uint2*)(g_atth + (size_t)row * MDIM);
    float4 v[4];
#pragma unroll
    for (int i = 0; i < 4; i++) v[i] = p[lane + 32 * i];
    float m = -INFINITY;
#pragma unroll
    for (int i = 0; i < 4; i++)
        m = fmaxf(m, fmaxf(fmaxf(v[i].x, v[i].y), fmaxf(v[i].z, v[i].w)));
    m = warp_max(m);
    float s = 0.0f;
#pragma unroll
    for (int i = 0; i < 4; i++) {
        v[i].x = expf(v[i].x - m); v[i].y = expf(v[i].y - m);
        v[i].z = expf(v[i].z - m); v[i].w = expf(v[i].w - m);
        s += v[i].x + v[i].y + v[i].z + v[i].w;
    }
    s = warp_sum(s);
    const float inv = 1.0f / s;
    float t = 0.0f;
#pragma unroll
    for (int i = 0; i < 4; i++) {
        v[i].x = fmaxf(v[i].x * inv - 0.0025f, 0.0f);
        v[i].y = fmaxf(v[i].y * inv - 0.0025f, 0.0f);
        v[i].z = fmaxf(v[i].z * inv - 0.0025f, 0.0f);
        v[i].w = fmaxf(v[i].w * inv - 0.0025f, 0.0f);
        t += v[i].x + v[i].y + v[i].z + v[i].w;
    }
    t = warp_sum(t);
    const float inv2 = 1.0f / fmaxf(t, 1e-12f);
#pragma unroll
    for (int i = 0; i < 4; i++) {
        v[i].x *= inv2; v[i].y *= inv2; v[i].z *= inv2; v[i].w *= inv2;
        p[lane + 32 * i] = v[i];
        ph[lane + 32 * i] = make_uint2(pack_half2(v[i].x, v[i].y),
                                       pack_half2(v[i].z, v[i].w));
    }
}

// att_channel_avg[n,m] = mean_c att[n*512+c, m]
__global__ __launch_bounds__(128) void chanmean_kernel(const float* __restrict__ att) {
    const int n = blockIdx.x;
    const int m = blockIdx.y * 128 + threadIdx.x;
    const float* base = att + ((size_t)n * 512) * MDIM + m;
    float s = 0.0f;
#pragma unroll 8
    for (int c = 0; c < 512; c++) s += base[(size_t)c * MDIM];
    g_avg[n * MDIM + m] = s * (1.0f / 512.0f);
}

// att_spatial broadcast
__global__ __launch_bounds__(256) void bcast_kernel(float* __restrict__ dst) {
    const int nm = blockIdx.x;
    const float v = g_avg[nm];
    float4 o = make_float4(v, v, v, v);
    ((float4*)(dst + (size_t)nm * SPATIAL))[threadIdx.x] = o;
}

// ============================================================================
extern "C" void kernel_launch(void* const* d_in, const int* in_sizes, int n_in,
                              void* d_out, int out_size) {
    (void)in_sizes; (void)n_in; (void)out_size;
    const float* x      = (const float*)d_in[0];
    const float* memory = (const float*)d_in[1];
    const float* w1     = (const float*)d_in[2];
    const float* b1     = (const float*)d_in[3];
    const float* w2     = (const float*)d_in[4];
    const float* b2     = (const float*)d_in[5];

    float* out = (float*)d_out;
    float* out_output  = out + OFF_OUTPUT;
    float* out_attsp   = out + OFF_ATTSP;
    float* out_inflat  = out + OFF_INFLAT;
    float* out_memnorm = out + OFF_MEMNORM;
    float* out_att     = out + OFF_ATT;

    float *p_h, *p_mp, *p_inv;
    __half *p_xh, *p_mnh, *p_mnTh, *p_atth;
    cudaGetSymbolAddress((void**)&p_h,    g_h);
    cudaGetSymbolAddress((void**)&p_mp,   g_memproc);
    cudaGetSymbolAddress((void**)&p_inv,  g_invnorm);
    cudaGetSymbolAddress((void**)&p_xh,   g_xh);
    cudaGetSymbolAddress((void**)&p_mnh,  g_mnh);
    cudaGetSymbolAddress((void**)&p_mnTh, g_mnTh);
    cudaGetSymbolAddress((void**)&p_atth, g_atth);

    cudaFuncSetAttribute((const void*)gemm_tc<true, true>,
                         cudaFuncAttributeMaxDynamicSharedMemorySize, GEMM_SMEM_BYTES);
    cudaFuncSetAttribute((const void*)gemm_fp16<true>,
                         cudaFuncAttributeMaxDynamicSharedMemorySize, HGEMM_SMEM_BYTES);
    cudaFuncSetAttribute((const void*)gemm_fp16<false>,
                         cudaFuncAttributeMaxDynamicSharedMemorySize, HGEMM_SMEM_BYTES);

    // input_flat = x (pure copy)
    cudaMemcpyAsync(out_inflat, x, (size_t)R_ROWS * SPATIAL * sizeof(float),
                    cudaMemcpyDeviceToDevice);

    // inverse L2 norms of x rows + fp16 conversion of x
    rowinv_cvt_kernel<<<R_ROWS / 8, 256>>>(x);

    // MLP: h = relu(memory @ w1^T + b1)   [512,512]  (tf32)
    gemm_tc<true, true><<<dim3(4, 4), 256, GEMM_SMEM_BYTES>>>(
        HIDDIM, SPATIAL, memory, w1, p_h, b1);
    // mem_proc = relu(h @ w2^T + b2)      [512,1024] (tf32)
    gemm_tc<true, true><<<dim3(8, 4), 256, GEMM_SMEM_BYTES>>>(
        SPATIAL, HIDDIM, p_h, w2, p_mp, b2);

    // memory_norm -> d_out (f32) + g_mnh (fp16)
    rownorm_kernel<<<MDIM, 256>>>(out_memnorm);
    // mnT (fp16) = transpose(memory_norm)
    transpose_kernel<<<dim3(SPATIAL / 32, MDIM / 32), 256>>>(out_memnorm);

    // S = diag(invnorm) * (x_h @ mn_h^T) -> att section (fp16 MMA, f32 accum)
    gemm_fp16<true><<<dim3(4, R_ROWS / 128), 256, HGEMM_SMEM_BYTES>>>(
        MDIM, SPATIAL, p_xh, p_mnh, out_att, p_inv);

    // softmax + shrink + L1 renorm (f32 in place) + fp16 copy
    softmax_shrink_kernel<<<R_ROWS / 8, 256>>>(out_att);

    // output = att_h @ mnT_h^T  [16384,1024]
    gemm_fp16<false><<<dim3(8, R_ROWS / 128), 256, HGEMM_SMEM_BYTES>>>(
        SPATIAL, MDIM, p_atth, p_mnTh, out_output, nullptr);

    // channel-mean of att + spatial broadcast
    chanmean_kernel<<<dim3(32, MDIM / 128), 128>>>(out_att);
    bcast_kernel<<<R_ROWS, 256>>>(out_attsp);
}

// round 7
// speedup vs baseline: 4.4703x; 1.2605x over previous
#include <cuda_runtime.h>
#include <cuda_fp16.h>
#include <cstdint>
#include <math.h>

// Problem constants
#define R_ROWS  16384   // N*C
#define SPATIAL 1024    // H*W
#define MDIM    512     // mem_dim
#define HIDDIM  512     // spatial/2

// d_out section offsets (floats)
#define OFF_OUTPUT   ((size_t)0)
#define OFF_ATTSP    ((size_t)16777216)
#define OFF_INFLAT   ((size_t)33554432)
#define OFF_MEMNORM  ((size_t)50331648)
#define OFF_ATT      ((size_t)50855936)

// Device scratch (allocation-free)
__device__ float  g_h[MDIM * HIDDIM];
__device__ float  g_memproc[MDIM * SPATIAL];
__device__ float  g_invnorm[R_ROWS];
__device__ __half g_xh[(size_t)R_ROWS * SPATIAL];    // fp16 x
__device__ __half g_mnh[MDIM * SPATIAL];             // fp16 memory_norm
__device__ __half g_mnTh[SPATIAL * MDIM];            // fp16 memory_norm^T
__device__ __half g_atth[(size_t)R_ROWS * MDIM];     // fp16 att

// ============================================================================
// mma.sync helpers (sm_80+ — base compute_103 target safe)
// ============================================================================
__device__ __forceinline__ void mma8_tf32(float* c, uint32_t a0, uint32_t a1,
                                          uint32_t a2, uint32_t a3,
                                          uint32_t b0, uint32_t b1) {
    asm volatile(
        "mma.sync.aligned.m16n8k8.row.col.f32.tf32.tf32.f32 "
        "{%0,%1,%2,%3}, {%4,%5,%6,%7}, {%8,%9}, {%0,%1,%2,%3};"
        : "+f"(c[0]), "+f"(c[1]), "+f"(c[2]), "+f"(c[3])
        : "r"(a0), "r"(a1), "r"(a2), "r"(a3), "r"(b0), "r"(b1));
}

__device__ __forceinline__ void mma16_f16(float* c, uint32_t a0, uint32_t a1,
                                          uint32_t a2, uint32_t a3,
                                          uint32_t b0, uint32_t b1) {
    asm volatile(
        "mma.sync.aligned.m16n8k16.row.col.f32.f16.f16.f32 "
        "{%0,%1,%2,%3}, {%4,%5,%6,%7}, {%8,%9}, {%0,%1,%2,%3};"
        : "+f"(c[0]), "+f"(c[1]), "+f"(c[2]), "+f"(c[3])
        : "r"(a0), "r"(a1), "r"(a2), "r"(a3), "r"(b0), "r"(b1));
}

__device__ __forceinline__ void ldmx4(uint32_t& r0, uint32_t& r1,
                                      uint32_t& r2, uint32_t& r3, uint32_t addr) {
    asm volatile("ldmatrix.sync.aligned.m8n8.x4.shared.b16 {%0,%1,%2,%3}, [%4];"
                 : "=r"(r0), "=r"(r1), "=r"(r2), "=r"(r3) : "r"(addr));
}

__device__ __forceinline__ uint32_t tf32_hi(float x) {
    uint32_t h;
    asm("cvt.rna.tf32.f32 %0, %1;" : "=r"(h) : "f"(x));
    return h;
}

__device__ __forceinline__ void cp16(uint32_t dst, const void* src) {
    asm volatile("cp.async.cg.shared.global [%0], [%1], 16;" :: "r"(dst), "l"(src));
}

__device__ __forceinline__ uint32_t pack_half2(float a, float b) {
    __half2 h = __floats2half2_rn(a, b);
    return *reinterpret_cast<uint32_t*>(&h);
}

__device__ __forceinline__ float warp_sum(float v) {
#pragma unroll
    for (int o = 16; o > 0; o >>= 1) v += __shfl_xor_sync(0xffffffffu, v, o);
    return v;
}
__device__ __forceinline__ float warp_max(float v) {
#pragma unroll
    for (int o = 16; o > 0; o >>= 1) v = fmaxf(v, __shfl_xor_sync(0xffffffffu, v, o));
    return v;
}

// ============================================================================
// tf32 NT GEMM tile (device fn) — precision-critical MLP path.
// CTA tile 128x128xBK32, 8 warps, 3-stage cp.async, 1 barrier per chunk.
// Always bias+relu epilogue.
// ============================================================================
#define SSTRIDE 36
#define TILEF   (128 * SSTRIDE)
#define STAGEF  (2 * TILEF)
#define GEMM_SMEM_BYTES (3 * STAGEF * 4)

__device__ void mlp_tile(
    int Ntot, int K,
    const float* __restrict__ A, const float* __restrict__ B,
    float* __restrict__ C, const float* __restrict__ bias,
    int bm, int bn)
{
    extern __shared__ float smf[];
    const uint32_t sbase = (uint32_t)__cvta_generic_to_shared(smf);
    const int tid  = threadIdx.x;
    const int wid  = tid >> 5;
    const int lane = tid & 31;
    const int wm   = wid & 1;
    const int wn   = wid >> 1;
    const int tr   = lane >> 2;
    const int tc   = lane & 3;

    const float* At = A + (size_t)bm * K;
    const float* Bt = B + (size_t)bn * K;
    const int nk = K >> 5;

    auto load_stage = [&](int st, int kc) {
        const uint32_t so = sbase + (uint32_t)(st * STAGEF * 4);
#pragma unroll
        for (int i = 0; i < 4; i++) {
            int u = tid + i * 256;
            int row = u >> 3;
            int seg = (u & 7) * 4;
            cp16(so + (uint32_t)((row * SSTRIDE + seg) * 4),
                 At + (size_t)row * K + kc * 32 + seg);
            cp16(so + (uint32_t)((TILEF + row * SSTRIDE + seg) * 4),
                 Bt + (size_t)row * K + kc * 32 + seg);
        }
        asm volatile("cp.async.commit_group;" ::: "memory");
    };

    float c[4][4][4];
#pragma unroll
    for (int mf = 0; mf < 4; mf++)
#pragma unroll
        for (int nf = 0; nf < 4; nf++)
#pragma unroll
            for (int q = 0; q < 4; q++) c[mf][nf][q] = 0.0f;

    load_stage(0, 0);
    load_stage(1, 1);

    for (int s = 0; s < nk; ++s) {
        if (s + 1 < nk) asm volatile("cp.async.wait_group 1;" ::: "memory");
        else            asm volatile("cp.async.wait_group 0;" ::: "memory");
        __syncthreads();
        if (s + 2 < nk) load_stage((s + 2) % 3, s + 2);

        const float* As = smf + (s % 3) * STAGEF;
        const float* Bs = As + TILEF;

#pragma unroll
        for (int kk = 0; kk < 4; kk++) {
            const int kb = kk * 8;
            uint32_t ah[4][4], bh[4][2];
#pragma unroll
            for (int mf = 0; mf < 4; mf++) {
                const int r0 = wm * 64 + mf * 16 + tr;
                ah[mf][0] = tf32_hi(As[r0 * SSTRIDE + kb + tc]);
                ah[mf][1] = tf32_hi(As[(r0 + 8) * SSTRIDE + kb + tc]);
                ah[mf][2] = tf32_hi(As[r0 * SSTRIDE + kb + tc + 4]);
                ah[mf][3] = tf32_hi(As[(r0 + 8) * SSTRIDE + kb + tc + 4]);
            }
#pragma unroll
            for (int nf = 0; nf < 4; nf++) {
                const int n0 = wn * 32 + nf * 8 + tr;
                bh[nf][0] = tf32_hi(Bs[n0 * SSTRIDE + kb + tc]);
                bh[nf][1] = tf32_hi(Bs[n0 * SSTRIDE + kb + tc + 4]);
            }
#pragma unroll
            for (int mf = 0; mf < 4; mf++)
#pragma unroll
                for (int nf = 0; nf < 4; nf++)
                    mma8_tf32(c[mf][nf], ah[mf][0], ah[mf][1], ah[mf][2], ah[mf][3],
                              bh[nf][0], bh[nf][1]);
        }
    }

#pragma unroll
    for (int mf = 0; mf < 4; mf++) {
        const int r0g = bm + wm * 64 + mf * 16 + tr;
#pragma unroll
        for (int nf = 0; nf < 4; nf++) {
            const int cg = bn + wn * 32 + nf * 8 + 2 * tc;
            float bb0 = bias[cg], bb1 = bias[cg + 1];
            float v0 = fmaxf(c[mf][nf][0] + bb0, 0.0f);
            float v1 = fmaxf(c[mf][nf][1] + bb1, 0.0f);
            float v2 = fmaxf(c[mf][nf][2] + bb0, 0.0f);
            float v3 = fmaxf(c[mf][nf][3] + bb1, 0.0f);
            *(float2*)&C[(size_t)r0g * Ntot + cg]       = make_float2(v0, v1);
            *(float2*)&C[(size_t)(r0g + 8) * Ntot + cg] = make_float2(v2, v3);
        }
    }
}

// ============================================================================
// fp16 NT GEMM tile (device fn, ldmatrix + 1-barrier pipeline)
// ============================================================================
#define SSW      20
#define HTILEW   (128 * SSW)
#define HSTAGEW  (2 * HTILEW)
#define HGEMM_SMEM_BYTES (3 * HSTAGEW * 4)

template <bool ROWSCALE>
__device__ void gemm16_tile(
    int Ntot, int K,
    const __half* __restrict__ A, const __half* __restrict__ B,
    float* __restrict__ C, const float* __restrict__ rowscale,
    int bm, int bn)
{
    extern __shared__ uint32_t smw[];
    const uint32_t sbase = (uint32_t)__cvta_generic_to_shared(smw);
    const int tid  = threadIdx.x;
    const int wid  = tid >> 5;
    const int lane = tid & 31;
    const int wm   = wid & 1;
    const int wn   = wid >> 1;
    const int tr   = lane >> 2;
    const int tc   = lane & 3;

    const __half* At = A + (size_t)bm * K;
    const __half* Bt = B + (size_t)bn * K;
    const int nk = K >> 5;

    const int q = lane >> 3;
    const int rsub = lane & 7;
    const int arow = wm * 64 + rsub + (q & 1) * 8;
    const int acolw = (q >> 1) * 4;
    const int brow = wn * 32 + rsub + (q >> 1) * 8;
    const int bcolw = (q & 1) * 4;

    auto load_stage = [&](int st, int kc) {
        const uint32_t so = sbase + (uint32_t)(st * HSTAGEW * 4);
#pragma unroll
        for (int i = 0; i < 2; i++) {
            int u = tid + i * 256;
            int row = u >> 2;
            int seg = (u & 3) * 4;
            cp16(so + (uint32_t)((row * SSW + seg) * 4),
                 At + (size_t)row * K + kc * 32 + seg * 2);
            cp16(so + (uint32_t)((HTILEW + row * SSW + seg) * 4),
                 Bt + (size_t)row * K + kc * 32 + seg * 2);
        }
        asm volatile("cp.async.commit_group;" ::: "memory");
    };

    float c[4][4][4];
#pragma unroll
    for (int mf = 0; mf < 4; mf++)
#pragma unroll
        for (int nf = 0; nf < 4; nf++)
#pragma unroll
            for (int qq = 0; qq < 4; qq++) c[mf][nf][qq] = 0.0f;

    load_stage(0, 0);
    load_stage(1, 1);

    for (int s = 0; s < nk; ++s) {
        if (s + 1 < nk) asm volatile("cp.async.wait_group 1;" ::: "memory");
        else            asm volatile("cp.async.wait_group 0;" ::: "memory");
        __syncthreads();
        if (s + 2 < nk) load_stage((s + 2) % 3, s + 2);

        const uint32_t stage = sbase + (uint32_t)((s % 3) * HSTAGEW * 4);
        const uint32_t aAddr0 = stage + (uint32_t)((arow * SSW + acolw) * 4);
        const uint32_t bAddr0 = stage + (uint32_t)((HTILEW + brow * SSW + bcolw) * 4);

#pragma unroll
        for (int kk = 0; kk < 2; kk++) {
            const uint32_t kboff = (uint32_t)(kk * 8 * 4);
            uint32_t a[4][4], b[4][2];
#pragma unroll
            for (int mf = 0; mf < 4; mf++)
                ldmx4(a[mf][0], a[mf][1], a[mf][2], a[mf][3],
                      aAddr0 + kboff + (uint32_t)(mf * 16 * SSW * 4));
#pragma unroll
            for (int nf2 = 0; nf2 < 2; nf2++)
                ldmx4(b[2 * nf2][0], b[2 * nf2][1], b[2 * nf2 + 1][0], b[2 * nf2 + 1][1],
                      bAddr0 + kboff + (uint32_t)(nf2 * 16 * SSW * 4));
#pragma unroll
            for (int mf = 0; mf < 4; mf++)
#pragma unroll
                for (int nf = 0; nf < 4; nf++)
                    mma16_f16(c[mf][nf], a[mf][0], a[mf][1], a[mf][2], a[mf][3],
                              b[nf][0], b[nf][1]);
        }
    }

#pragma unroll
    for (int mf = 0; mf < 4; mf++) {
        const int r0g = bm + wm * 64 + mf * 16 + tr;
        const float rs0 = ROWSCALE ? rowscale[r0g] : 1.0f;
        const float rs1 = ROWSCALE ? rowscale[r0g + 8] : 1.0f;
#pragma unroll
        for (int nf = 0; nf < 4; nf++) {
            const int cg = bn + wn * 32 + nf * 8 + 2 * tc;
            float v0 = c[mf][nf][0], v1 = c[mf][nf][1];
            float v2 = c[mf][nf][2], v3 = c[mf][nf][3];
            if (ROWSCALE) { v0 *= rs0; v1 *= rs0; v2 *= rs1; v3 *= rs1; }
            *(float2*)&C[(size_t)r0g * Ntot + cg]       = make_float2(v0, v1);
            *(float2*)&C[(size_t)(r0g + 8) * Ntot + cg] = make_float2(v2, v3);
        }
    }
}

// ============================================================================
// Fused input processing: copy x -> input_flat, fp16(x) -> g_xh, invnorm.
// Warp per row, persistent over [base, base+8192).
// ============================================================================
__device__ void input_rows(const float* __restrict__ x, float* __restrict__ inflat,
                           int gwarp, int nwarps, int base) {
    const int lane = threadIdx.x & 31;
    for (int row = base + gwarp; row < base + 8192; row += nwarps) {
        const float4* p = (const float4*)(x + (size_t)row * SPATIAL);
        float4* of = (float4*)(inflat + (size_t)row * SPATIAL);
        uint2*  xo = (uint2*)(g_xh + (size_t)row * SPATIAL);
        float s = 0.0f;
#pragma unroll
        for (int i = 0; i < 8; i++) {
            float4 v = p[lane + 32 * i];
            s += v.x * v.x + v.y * v.y + v.z * v.z + v.w * v.w;
            of[lane + 32 * i] = v;
            xo[lane + 32 * i] = make_uint2(pack_half2(v.x, v.y), pack_half2(v.z, v.w));
        }
        s = warp_sum(s);
        if (lane == 0) g_invnorm[row] = 1.0f / fmaxf(sqrtf(s), 1e-12f);
    }
}

// K1: MLP1 (16 CTAs) + input rows 0..8191 (132 CTAs)
__global__ void __launch_bounds__(256, 1) k1_mlp1_input(
    const float* __restrict__ memory, const float* __restrict__ w1,
    const float* __restrict__ b1, const float* __restrict__ x,
    float* __restrict__ inflat)
{
    const int b = blockIdx.x;
    if (b < 16) {
        mlp_tile(HIDDIM, SPATIAL, memory, w1, g_h, b1, (b >> 2) * 128, (b & 3) * 128);
    } else {
        const int gwarp = (b - 16) * 8 + (threadIdx.x >> 5);
        input_rows(x, inflat, gwarp, 132 * 8, 0);
    }
}

// K2: MLP2 (32 CTAs) + input rows 8192..16383 (116 CTAs)
__global__ void __launch_bounds__(256, 1) k2_mlp2_input(
    const float* __restrict__ w2, const float* __restrict__ b2,
    const float* __restrict__ x, float* __restrict__ inflat)
{
    const int b = blockIdx.x;
    if (b < 32) {
        mlp_tile(SPATIAL, HIDDIM, g_h, w2, g_memproc, b2, (b >> 3) * 128, (b & 7) * 128);
    } else {
        const int gwarp = (b - 32) * 8 + (threadIdx.x >> 5);
        input_rows(x, inflat, gwarp, 116 * 8, 8192);
    }
}

// ============================================================================
// rownorm + fp16 + transposed fp16 in one pass. Block per row.
// ============================================================================
__global__ __launch_bounds__(256) void rownorm_t_kernel(float* __restrict__ dst) {
    __shared__ float sm[8];
    const int row  = blockIdx.x;
    const int tid  = threadIdx.x;
    const int lane = tid & 31;
    const int w    = tid >> 5;
    const float4* p = (const float4*)(g_memproc + (size_t)row * SPATIAL);
    float4 v = p[tid];
    float s = v.x * v.x + v.y * v.y + v.z * v.z + v.w * v.w;
    s = warp_sum(s);
    if (lane == 0) sm[w] = s;
    __syncthreads();
    float tot = 0.0f;
#pragma unroll
    for (int i = 0; i < 8; i++) tot += sm[i];
    const float sc = 1.0f / fmaxf(sqrtf(tot), 1e-12f);
    float4 o = make_float4(v.x * sc, v.y * sc, v.z * sc, v.w * sc);
    ((float4*)(dst + (size_t)row * SPATIAL))[tid] = o;
    ((uint2*)(g_mnh + (size_t)row * SPATIAL))[tid] =
        make_uint2(pack_half2(o.x, o.y), pack_half2(o.z, o.w));
    // transposed fp16 scatter
    g_mnTh[(size_t)(4 * tid + 0) * MDIM + row] = __float2half_rn(o.x);
    g_mnTh[(size_t)(4 * tid + 1) * MDIM + row] = __float2half_rn(o.y);
    g_mnTh[(size_t)(4 * tid + 2) * MDIM + row] = __float2half_rn(o.z);
    g_mnTh[(size_t)(4 * tid + 3) * MDIM + row] = __float2half_rn(o.w);
}

// ============================================================================
// GEMM3: S = diag(invnorm) * (xh @ mnh^T) -> att (f32)
// ============================================================================
__global__ void __launch_bounds__(256, 1) gemm3_kernel(float* __restrict__ att) {
    const int b = blockIdx.x;
    gemm16_tile<true>(MDIM, SPATIAL, g_xh, g_mnh, att, g_invnorm,
                      (b >> 2) * 128, (b & 3) * 128);
}

// ============================================================================
// softmax + shrink + L1 renorm, in place (f32) + fp16 copy. Warp per row.
// ============================================================================
__global__ __launch_bounds__(256) void softmax_shrink_kernel(float* __restrict__ S) {
    const int row  = blockIdx.x * 8 + (threadIdx.x >> 5);
    const int lane = threadIdx.x & 31;
    float4* p = (float4*)(S + (size_t)row * MDIM);
    uint2* ph = (uint2*)(g_atth + (size_t)row * MDIM);
    float4 v[4];
#pragma unroll
    for (int i = 0; i < 4; i++) v[i] = p[lane + 32 * i];
    float m = -INFINITY;
#pragma unroll
    for (int i = 0; i < 4; i++)
        m = fmaxf(m, fmaxf(fmaxf(v[i].x, v[i].y), fmaxf(v[i].z, v[i].w)));
    m = warp_max(m);
    float s = 0.0f;
#pragma unroll
    for (int i = 0; i < 4; i++) {
        v[i].x = expf(v[i].x - m); v[i].y = expf(v[i].y - m);
        v[i].z = expf(v[i].z - m); v[i].w = expf(v[i].w - m);
        s += v[i].x + v[i].y + v[i].z + v[i].w;
    }
    s = warp_sum(s);
    const float inv = 1.0f / s;
    float t = 0.0f;
#pragma unroll
    for (int i = 0; i < 4; i++) {
        v[i].x = fmaxf(v[i].x * inv - 0.0025f, 0.0f);
        v[i].y = fmaxf(v[i].y * inv - 0.0025f, 0.0f);
        v[i].z = fmaxf(v[i].z * inv - 0.0025f, 0.0f);
        v[i].w = fmaxf(v[i].w * inv - 0.0025f, 0.0f);
        t += v[i].x + v[i].y + v[i].z + v[i].w;
    }
    t = warp_sum(t);
    const float inv2 = 1.0f / fmaxf(t, 1e-12f);
#pragma unroll
    for (int i = 0; i < 4; i++) {
        v[i].x *= inv2; v[i].y *= inv2; v[i].z *= inv2; v[i].w *= inv2;
        p[lane + 32 * i] = v[i];
        ph[lane + 32 * i] = make_uint2(pack_half2(v[i].x, v[i].y),
                                       pack_half2(v[i].z, v[i].w));
    }
}

// ============================================================================
// K4: tail blocks (chanmean+bcast, 128) first, then GEMM4 (1024 blocks)
// ============================================================================
__global__ void __launch_bounds__(256, 1) k4_gemm4_tail(
    float* __restrict__ outp, float* __restrict__ attsp)
{
    const int b = blockIdx.x;
    if (b >= 128) {
        const int g = b - 128;
        gemm16_tile<false>(SPATIAL, MDIM, g_atth, g_mnTh, outp, nullptr,
                           (g >> 3) * 128, (g & 7) * 128);
        return;
    }
    // tail: channel-mean over 512 channels + spatial broadcast
    extern __shared__ float sf[];
    const int n  = b >> 2;          // 0..31
    const int mg = b & 3;           // 0..3 (128-col group)
    const int t  = threadIdx.x;
    const int m  = t & 127;
    const int ch = t >> 7;          // 0/1 -> channel halves
    const __half* base = g_atth + ((size_t)(n * 512 + ch * 256)) * MDIM + mg * 128 + m;
    float s = 0.0f;
#pragma unroll 4
    for (int c = 0; c < 256; c++) s += __half2float(base[(size_t)c * MDIM]);
    sf[t] = s;
    __syncthreads();
    if (t < 128) sf[256 + t] = (sf[t] + sf[t + 128]) * (1.0f / 512.0f);
    __syncthreads();
    float* dst0 = attsp + ((size_t)(n * MDIM + mg * 128)) * SPATIAL;
    for (int m2 = 0; m2 < 128; m2++) {
        const float v = sf[256 + m2];
        ((float4*)(dst0 + (size_t)m2 * SPATIAL))[t] = make_float4(v, v, v, v);
    }
}

// ============================================================================
extern "C" void kernel_launch(void* const* d_in, const int* in_sizes, int n_in,
                              void* d_out, int out_size) {
    (void)in_sizes; (void)n_in; (void)out_size;
    const float* x      = (const float*)d_in[0];
    const float* memory = (const float*)d_in[1];
    const float* w1     = (const float*)d_in[2];
    const float* b1     = (const float*)d_in[3];
    const float* w2     = (const float*)d_in[4];
    const float* b2     = (const float*)d_in[5];

    float* out = (float*)d_out;
    float* out_output  = out + OFF_OUTPUT;
    float* out_attsp   = out + OFF_ATTSP;
    float* out_inflat  = out + OFF_INFLAT;
    float* out_memnorm = out + OFF_MEMNORM;
    float* out_att     = out + OFF_ATT;

    cudaFuncSetAttribute((const void*)k1_mlp1_input,
                         cudaFuncAttributeMaxDynamicSharedMemorySize, GEMM_SMEM_BYTES);
    cudaFuncSetAttribute((const void*)k2_mlp2_input,
                         cudaFuncAttributeMaxDynamicSharedMemorySize, GEMM_SMEM_BYTES);
    cudaFuncSetAttribute((const void*)gemm3_kernel,
                         cudaFuncAttributeMaxDynamicSharedMemorySize, HGEMM_SMEM_BYTES);
    cudaFuncSetAttribute((const void*)k4_gemm4_tail,
                         cudaFuncAttributeMaxDynamicSharedMemorySize, HGEMM_SMEM_BYTES);

    // K1: MLP layer 1 || input processing (rows 0..8191)
    k1_mlp1_input<<<148, 256, GEMM_SMEM_BYTES>>>(memory, w1, b1, x, out_inflat);
    // K2: MLP layer 2 || input processing (rows 8192..16383)
    k2_mlp2_input<<<148, 256, GEMM_SMEM_BYTES>>>(w2, b2, x, out_inflat);
    // memory_norm (f32 + fp16 + fp16-transposed)
    rownorm_t_kernel<<<MDIM, 256>>>(out_memnorm);
    // addressing logits -> att section
    gemm3_kernel<<<512, 256, HGEMM_SMEM_BYTES>>>(out_att);
    // softmax + shrink + renorm (+ fp16 att)
    softmax_shrink_kernel<<<R_ROWS / 8, 256>>>(out_att);
    // output GEMM + fused channel-mean/broadcast
    k4_gemm4_tail<<<1152, 256, HGEMM_SMEM_BYTES>>>(out_output, out_attsp);
}

// round 8
// speedup vs baseline: 5.1678x; 1.1560x over previous
#include <cuda_runtime.h>
#include <cuda_fp16.h>
#include <cstdint>
#include <math.h>

// Problem constants
#define R_ROWS  16384   // N*C
#define SPATIAL 1024    // H*W
#define MDIM    512     // mem_dim
#define HIDDIM  512     // spatial/2

// d_out section offsets (floats)
#define OFF_OUTPUT   ((size_t)0)
#define OFF_ATTSP    ((size_t)16777216)
#define OFF_INFLAT   ((size_t)33554432)
#define OFF_MEMNORM  ((size_t)50331648)
#define OFF_ATT      ((size_t)50855936)

// Device scratch (allocation-free)
__device__ float  g_h[MDIM * HIDDIM];
__device__ float  g_memproc[MDIM * SPATIAL];
__device__ float  g_invnorm[R_ROWS];
__device__ __half g_xh[(size_t)R_ROWS * SPATIAL];    // fp16 x
__device__ __half g_mnh[MDIM * SPATIAL];             // fp16 memory_norm
__device__ __half g_mnTh[SPATIAL * MDIM];            // fp16 memory_norm^T
__device__ __half g_atth[(size_t)R_ROWS * MDIM];     // fp16 att

// ============================================================================
// mma.sync helpers (sm_80+ — base compute_103 target safe)
// ============================================================================
__device__ __forceinline__ void mma8_tf32(float* c, uint32_t a0, uint32_t a1,
                                          uint32_t a2, uint32_t a3,
                                          uint32_t b0, uint32_t b1) {
    asm volatile(
        "mma.sync.aligned.m16n8k8.row.col.f32.tf32.tf32.f32 "
        "{%0,%1,%2,%3}, {%4,%5,%6,%7}, {%8,%9}, {%0,%1,%2,%3};"
        : "+f"(c[0]), "+f"(c[1]), "+f"(c[2]), "+f"(c[3])
        : "r"(a0), "r"(a1), "r"(a2), "r"(a3), "r"(b0), "r"(b1));
}

__device__ __forceinline__ void mma16_f16(float* c, uint32_t a0, uint32_t a1,
                                          uint32_t a2, uint32_t a3,
                                          uint32_t b0, uint32_t b1) {
    asm volatile(
        "mma.sync.aligned.m16n8k16.row.col.f32.f16.f16.f32 "
        "{%0,%1,%2,%3}, {%4,%5,%6,%7}, {%8,%9}, {%0,%1,%2,%3};"
        : "+f"(c[0]), "+f"(c[1]), "+f"(c[2]), "+f"(c[3])
        : "r"(a0), "r"(a1), "r"(a2), "r"(a3), "r"(b0), "r"(b1));
}

__device__ __forceinline__ void ldmx4(uint32_t& r0, uint32_t& r1,
                                      uint32_t& r2, uint32_t& r3, uint32_t addr) {
    asm volatile("ldmatrix.sync.aligned.m8n8.x4.shared.b16 {%0,%1,%2,%3}, [%4];"
                 : "=r"(r0), "=r"(r1), "=r"(r2), "=r"(r3) : "r"(addr));
}

__device__ __forceinline__ uint32_t tf32_hi(float x) {
    uint32_t h;
    asm("cvt.rna.tf32.f32 %0, %1;" : "=r"(h) : "f"(x));
    return h;
}

__device__ __forceinline__ void cp16(uint32_t dst, const void* src) {
    asm volatile("cp.async.cg.shared.global [%0], [%1], 16;" :: "r"(dst), "l"(src));
}

__device__ __forceinline__ uint32_t pack_half2(float a, float b) {
    __half2 h = __floats2half2_rn(a, b);
    return *reinterpret_cast<uint32_t*>(&h);
}

__device__ __forceinline__ float warp_sum(float v) {
#pragma unroll
    for (int o = 16; o > 0; o >>= 1) v += __shfl_xor_sync(0xffffffffu, v, o);
    return v;
}
__device__ __forceinline__ float warp_max(float v) {
#pragma unroll
    for (int o = 16; o > 0; o >>= 1) v = fmaxf(v, __shfl_xor_sync(0xffffffffu, v, o));
    return v;
}

// ============================================================================
// tf32 NT GEMM tile (device fn) — precision-critical MLP path.
// CTA tile 128x128xBK32, 8 warps, 3-stage cp.async, 1 barrier per chunk.
// ============================================================================
#define SSTRIDE 36
#define TILEF   (128 * SSTRIDE)
#define STAGEF  (2 * TILEF)
#define GEMM_SMEM_BYTES (3 * STAGEF * 4)

__device__ void mlp_tile(
    int Ntot, int K,
    const float* __restrict__ A, const float* __restrict__ B,
    float* __restrict__ C, const float* __restrict__ bias,
    int bm, int bn)
{
    extern __shared__ float smf[];
    const uint32_t sbase = (uint32_t)__cvta_generic_to_shared(smf);
    const int tid  = threadIdx.x;
    const int wid  = tid >> 5;
    const int lane = tid & 31;
    const int wm   = wid & 1;
    const int wn   = wid >> 1;
    const int tr   = lane >> 2;
    const int tc   = lane & 3;

    const float* At = A + (size_t)bm * K;
    const float* Bt = B + (size_t)bn * K;
    const int nk = K >> 5;

    auto load_stage = [&](int st, int kc) {
        const uint32_t so = sbase + (uint32_t)(st * STAGEF * 4);
#pragma unroll
        for (int i = 0; i < 4; i++) {
            int u = tid + i * 256;
            int row = u >> 3;
            int seg = (u & 7) * 4;
            cp16(so + (uint32_t)((row * SSTRIDE + seg) * 4),
                 At + (size_t)row * K + kc * 32 + seg);
            cp16(so + (uint32_t)((TILEF + row * SSTRIDE + seg) * 4),
                 Bt + (size_t)row * K + kc * 32 + seg);
        }
        asm volatile("cp.async.commit_group;" ::: "memory");
    };

    float c[4][4][4];
#pragma unroll
    for (int mf = 0; mf < 4; mf++)
#pragma unroll
        for (int nf = 0; nf < 4; nf++)
#pragma unroll
            for (int q = 0; q < 4; q++) c[mf][nf][q] = 0.0f;

    load_stage(0, 0);
    load_stage(1, 1);

    for (int s = 0; s < nk; ++s) {
        if (s + 1 < nk) asm volatile("cp.async.wait_group 1;" ::: "memory");
        else            asm volatile("cp.async.wait_group 0;" ::: "memory");
        __syncthreads();
        if (s + 2 < nk) load_stage((s + 2) % 3, s + 2);

        const float* As = smf + (s % 3) * STAGEF;
        const float* Bs = As + TILEF;

#pragma unroll
        for (int kk = 0; kk < 4; kk++) {
            const int kb = kk * 8;
            uint32_t ah[4][4], bh[4][2];
#pragma unroll
            for (int mf = 0; mf < 4; mf++) {
                const int r0 = wm * 64 + mf * 16 + tr;
                ah[mf][0] = tf32_hi(As[r0 * SSTRIDE + kb + tc]);
                ah[mf][1] = tf32_hi(As[(r0 + 8) * SSTRIDE + kb + tc]);
                ah[mf][2] = tf32_hi(As[r0 * SSTRIDE + kb + tc + 4]);
                ah[mf][3] = tf32_hi(As[(r0 + 8) * SSTRIDE + kb + tc + 4]);
            }
#pragma unroll
            for (int nf = 0; nf < 4; nf++) {
                const int n0 = wn * 32 + nf * 8 + tr;
                bh[nf][0] = tf32_hi(Bs[n0 * SSTRIDE + kb + tc]);
                bh[nf][1] = tf32_hi(Bs[n0 * SSTRIDE + kb + tc + 4]);
            }
#pragma unroll
            for (int mf = 0; mf < 4; mf++)
#pragma unroll
                for (int nf = 0; nf < 4; nf++)
                    mma8_tf32(c[mf][nf], ah[mf][0], ah[mf][1], ah[mf][2], ah[mf][3],
                              bh[nf][0], bh[nf][1]);
        }
    }

#pragma unroll
    for (int mf = 0; mf < 4; mf++) {
        const int r0g = bm + wm * 64 + mf * 16 + tr;
#pragma unroll
        for (int nf = 0; nf < 4; nf++) {
            const int cg = bn + wn * 32 + nf * 8 + 2 * tc;
            float bb0 = bias[cg], bb1 = bias[cg + 1];
            float v0 = fmaxf(c[mf][nf][0] + bb0, 0.0f);
            float v1 = fmaxf(c[mf][nf][1] + bb1, 0.0f);
            float v2 = fmaxf(c[mf][nf][2] + bb0, 0.0f);
            float v3 = fmaxf(c[mf][nf][3] + bb1, 0.0f);
            *(float2*)&C[(size_t)r0g * Ntot + cg]       = make_float2(v0, v1);
            *(float2*)&C[(size_t)(r0g + 8) * Ntot + cg] = make_float2(v2, v3);
        }
    }
}

// ============================================================================
// fp16 NT GEMM tile: 2-stage pipeline, smem 40KB -> 2 CTAs/SM.
// One barrier per chunk; WAR-safe (next-load issued after the barrier that
// follows the compute which read that buffer).
// ============================================================================
#define SSW      20
#define HTILEW   (128 * SSW)
#define HSTAGEW  (2 * HTILEW)
#define HGEMM_SMEM_BYTES (2 * HSTAGEW * 4)   // 40960 B

template <bool ROWSCALE>
__device__ void gemm16_tile(
    int Ntot, int K,
    const __half* __restrict__ A, const __half* __restrict__ B,
    float* __restrict__ C, const float* __restrict__ rowscale,
    int bm, int bn)
{
    extern __shared__ uint32_t smw[];
    const uint32_t sbase = (uint32_t)__cvta_generic_to_shared(smw);
    const int tid  = threadIdx.x;
    const int wid  = tid >> 5;
    const int lane = tid & 31;
    const int wm   = wid & 1;
    const int wn   = wid >> 1;
    const int tr   = lane >> 2;
    const int tc   = lane & 3;

    const __half* At = A + (size_t)bm * K;
    const __half* Bt = B + (size_t)bn * K;
    const int nk = K >> 5;

    const int q = lane >> 3;
    const int rsub = lane & 7;
    const int arow = wm * 64 + rsub + (q & 1) * 8;
    const int acolw = (q >> 1) * 4;
    const int brow = wn * 32 + rsub + (q >> 1) * 8;
    const int bcolw = (q & 1) * 4;

    auto load_stage = [&](int st, int kc) {
        const uint32_t so = sbase + (uint32_t)(st * HSTAGEW * 4);
#pragma unroll
        for (int i = 0; i < 2; i++) {
            int u = tid + i * 256;
            int row = u >> 2;
            int seg = (u & 3) * 4;
            cp16(so + (uint32_t)((row * SSW + seg) * 4),
                 At + (size_t)row * K + kc * 32 + seg * 2);
            cp16(so + (uint32_t)((HTILEW + row * SSW + seg) * 4),
                 Bt + (size_t)row * K + kc * 32 + seg * 2);
        }
        asm volatile("cp.async.commit_group;" ::: "memory");
    };

    float c[4][4][4];
#pragma unroll
    for (int mf = 0; mf < 4; mf++)
#pragma unroll
        for (int nf = 0; nf < 4; nf++)
#pragma unroll
            for (int qq = 0; qq < 4; qq++) c[mf][nf][qq] = 0.0f;

    load_stage(0, 0);

    for (int s = 0; s < nk; ++s) {
        asm volatile("cp.async.wait_group 0;" ::: "memory");
        __syncthreads();
        if (s + 1 < nk) load_stage((s + 1) & 1, s + 1);

        const uint32_t stage = sbase + (uint32_t)((s & 1) * HSTAGEW * 4);
        const uint32_t aAddr0 = stage + (uint32_t)((arow * SSW + acolw) * 4);
        const uint32_t bAddr0 = stage + (uint32_t)((HTILEW + brow * SSW + bcolw) * 4);

#pragma unroll
        for (int kk = 0; kk < 2; kk++) {
            const uint32_t kboff = (uint32_t)(kk * 8 * 4);
            uint32_t a[4][4], b[4][2];
#pragma unroll
            for (int mf = 0; mf < 4; mf++)
                ldmx4(a[mf][0], a[mf][1], a[mf][2], a[mf][3],
                      aAddr0 + kboff + (uint32_t)(mf * 16 * SSW * 4));
#pragma unroll
            for (int nf2 = 0; nf2 < 2; nf2++)
                ldmx4(b[2 * nf2][0], b[2 * nf2][1], b[2 * nf2 + 1][0], b[2 * nf2 + 1][1],
                      bAddr0 + kboff + (uint32_t)(nf2 * 16 * SSW * 4));
#pragma unroll
            for (int mf = 0; mf < 4; mf++)
#pragma unroll
                for (int nf = 0; nf < 4; nf++)
                    mma16_f16(c[mf][nf], a[mf][0], a[mf][1], a[mf][2], a[mf][3],
                              b[nf][0], b[nf][1]);
        }
    }

#pragma unroll
    for (int mf = 0; mf < 4; mf++) {
        const int r0g = bm + wm * 64 + mf * 16 + tr;
        const float rs0 = ROWSCALE ? rowscale[r0g] : 1.0f;
        const float rs1 = ROWSCALE ? rowscale[r0g + 8] : 1.0f;
#pragma unroll
        for (int nf = 0; nf < 4; nf++) {
            const int cg = bn + wn * 32 + nf * 8 + 2 * tc;
            float v0 = c[mf][nf][0], v1 = c[mf][nf][1];
            float v2 = c[mf][nf][2], v3 = c[mf][nf][3];
            if (ROWSCALE) { v0 *= rs0; v1 *= rs0; v2 *= rs1; v3 *= rs1; }
            *(float2*)&C[(size_t)r0g * Ntot + cg]       = make_float2(v0, v1);
            *(float2*)&C[(size_t)(r0g + 8) * Ntot + cg] = make_float2(v2, v3);
        }
    }
}

// ============================================================================
// Fused input processing: copy x -> input_flat, fp16(x) -> g_xh, invnorm.
// ============================================================================
__device__ void input_rows(const float* __restrict__ x, float* __restrict__ inflat,
                           int gwarp, int nwarps, int base) {
    const int lane = threadIdx.x & 31;
    for (int row = base + gwarp; row < base + 8192; row += nwarps) {
        const float4* p = (const float4*)(x + (size_t)row * SPATIAL);
        float4* of = (float4*)(inflat + (size_t)row * SPATIAL);
        uint2*  xo = (uint2*)(g_xh + (size_t)row * SPATIAL);
        float s = 0.0f;
#pragma unroll
        for (int i = 0; i < 8; i++) {
            float4 v = p[lane + 32 * i];
            s += v.x * v.x + v.y * v.y + v.z * v.z + v.w * v.w;
            of[lane + 32 * i] = v;
            xo[lane + 32 * i] = make_uint2(pack_half2(v.x, v.y), pack_half2(v.z, v.w));
        }
        s = warp_sum(s);
        if (lane == 0) g_invnorm[row] = 1.0f / fmaxf(sqrtf(s), 1e-12f);
    }
}

// K1: MLP1 (16 CTAs) + input rows 0..8191 (132 CTAs)
__global__ void __launch_bounds__(256, 1) k1_mlp1_input(
    const float* __restrict__ memory, const float* __restrict__ w1,
    const float* __restrict__ b1, const float* __restrict__ x,
    float* __restrict__ inflat)
{
    const int b = blockIdx.x;
    if (b < 16) {
        mlp_tile(HIDDIM, SPATIAL, memory, w1, g_h, b1, (b >> 2) * 128, (b & 3) * 128);
    } else {
        const int gwarp = (b - 16) * 8 + (threadIdx.x >> 5);
        input_rows(x, inflat, gwarp, 132 * 8, 0);
    }
}

// K2: MLP2 (32 CTAs) + input rows 8192..16383 (116 CTAs)
__global__ void __launch_bounds__(256, 1) k2_mlp2_input(
    const float* __restrict__ w2, const float* __restrict__ b2,
    const float* __restrict__ x, float* __restrict__ inflat)
{
    const int b = blockIdx.x;
    if (b < 32) {
        mlp_tile(SPATIAL, HIDDIM, g_h, w2, g_memproc, b2, (b >> 3) * 128, (b & 7) * 128);
    } else {
        const int gwarp = (b - 32) * 8 + (threadIdx.x >> 5);
        input_rows(x, inflat, gwarp, 116 * 8, 8192);
    }
}

// ============================================================================
// rownorm + fp16 + transposed fp16 in one pass. Block per row.
// ============================================================================
__global__ __launch_bounds__(256) void rownorm_t_kernel(float* __restrict__ dst) {
    __shared__ float sm[8];
    const int row  = blockIdx.x;
    const int tid  = threadIdx.x;
    const int lane = tid & 31;
    const int w    = tid >> 5;
    const float4* p = (const float4*)(g_memproc + (size_t)row * SPATIAL);
    float4 v = p[tid];
    float s = v.x * v.x + v.y * v.y + v.z * v.z + v.w * v.w;
    s = warp_sum(s);
    if (lane == 0) sm[w] = s;
    __syncthreads();
    float tot = 0.0f;
#pragma unroll
    for (int i = 0; i < 8; i++) tot += sm[i];
    const float sc = 1.0f / fmaxf(sqrtf(tot), 1e-12f);
    float4 o = make_float4(v.x * sc, v.y * sc, v.z * sc, v.w * sc);
    ((float4*)(dst + (size_t)row * SPATIAL))[tid] = o;
    ((uint2*)(g_mnh + (size_t)row * SPATIAL))[tid] =
        make_uint2(pack_half2(o.x, o.y), pack_half2(o.z, o.w));
    g_mnTh[(size_t)(4 * tid + 0) * MDIM + row] = __float2half_rn(o.x);
    g_mnTh[(size_t)(4 * tid + 1) * MDIM + row] = __float2half_rn(o.y);
    g_mnTh[(size_t)(4 * tid + 2) * MDIM + row] = __float2half_rn(o.z);
    g_mnTh[(size_t)(4 * tid + 3) * MDIM + row] = __float2half_rn(o.w);
}

// ============================================================================
// GEMM3: S = diag(invnorm) * (xh @ mnh^T) -> att (f32)
// ============================================================================
__global__ void __launch_bounds__(256, 2) gemm3_kernel(float* __restrict__ att) {
    const int b = blockIdx.x;
    gemm16_tile<true>(MDIM, SPATIAL, g_xh, g_mnh, att, g_invnorm,
                      (b >> 2) * 128, (b & 3) * 128);
}

// ============================================================================
// softmax + shrink + L1 renorm, in place (f32) + fp16 copy. Warp per row.
// ============================================================================
__global__ __launch_bounds__(256) void softmax_shrink_kernel(float* __restrict__ S) {
    const int row  = blockIdx.x * 8 + (threadIdx.x >> 5);
    const int lane = threadIdx.x & 31;
    float4* p = (float4*)(S + (size_t)row * MDIM);
    uint2* ph = (uint2*)(g_atth + (size_t)row * MDIM);
    float4 v[4];
#pragma unroll
    for (int i = 0; i < 4; i++) v[i] = p[lane + 32 * i];
    float m = -INFINITY;
#pragma unroll
    for (int i = 0; i < 4; i++)
        m = fmaxf(m, fmaxf(fmaxf(v[i].x, v[i].y), fmaxf(v[i].z, v[i].w)));
    m = warp_max(m);
    float s = 0.0f;
#pragma unroll
    for (int i = 0; i < 4; i++) {
        v[i].x = expf(v[i].x - m); v[i].y = expf(v[i].y - m);
        v[i].z = expf(v[i].z - m); v[i].w = expf(v[i].w - m);
        s += v[i].x + v[i].y + v[i].z + v[i].w;
    }
    s = warp_sum(s);
    const float inv = 1.0f / s;
    float t = 0.0f;
#pragma unroll
    for (int i = 0; i < 4; i++) {
        v[i].x = fmaxf(v[i].x * inv - 0.0025f, 0.0f);
        v[i].y = fmaxf(v[i].y * inv - 0.0025f, 0.0f);
        v[i].z = fmaxf(v[i].z * inv - 0.0025f, 0.0f);
        v[i].w = fmaxf(v[i].w * inv - 0.0025f, 0.0f);
        t += v[i].x + v[i].y + v[i].z + v[i].w;
    }
    t = warp_sum(t);
    const float inv2 = 1.0f / fmaxf(t, 1e-12f);
#pragma unroll
    for (int i = 0; i < 4; i++) {
        v[i].x *= inv2; v[i].y *= inv2; v[i].z *= inv2; v[i].w *= inv2;
        p[lane + 32 * i] = v[i];
        ph[lane + 32 * i] = make_uint2(pack_half2(v[i].x, v[i].y),
                                       pack_half2(v[i].z, v[i].w));
    }
}

// ============================================================================
// K4: tail blocks (chanmean+bcast, 128) first, then GEMM4 (1024 blocks)
// ============================================================================
__global__ void __launch_bounds__(256, 2) k4_gemm4_tail(
    float* __restrict__ outp, float* __restrict__ attsp)
{
    const int b = blockIdx.x;
    if (b >= 128) {
        const int g = b - 128;
        gemm16_tile<false>(SPATIAL, MDIM, g_atth, g_mnTh, outp, nullptr,
                           (g >> 3) * 128, (g & 7) * 128);
        return;
    }
    extern __shared__ float sf[];
    const int n  = b >> 2;
    const int mg = b & 3;
    const int t  = threadIdx.x;
    const int m  = t & 127;
    const int ch = t >> 7;
    const __half* base = g_atth + ((size_t)(n * 512 + ch * 256)) * MDIM + mg * 128 + m;
    float s = 0.0f;
#pragma unroll 4
    for (int c = 0; c < 256; c++) s += __half2float(base[(size_t)c * MDIM]);
    sf[t] = s;
    __syncthreads();
    if (t < 128) sf[256 + t] = (sf[t] + sf[t + 128]) * (1.0f / 512.0f);
    __syncthreads();
    float* dst0 = attsp + ((size_t)(n * MDIM + mg * 128)) * SPATIAL;
    for (int m2 = 0; m2 < 128; m2++) {
        const float v = sf[256 + m2];
        ((float4*)(dst0 + (size_t)m2 * SPATIAL))[t] = make_float4(v, v, v, v);
    }
}

// ============================================================================
extern "C" void kernel_launch(void* const* d_in, const int* in_sizes, int n_in,
                              void* d_out, int out_size) {
    (void)in_sizes; (void)n_in; (void)out_size;
    const float* x      = (const float*)d_in[0];
    const float* memory = (const float*)d_in[1];
    const float* w1     = (const float*)d_in[2];
    const float* b1     = (const float*)d_in[3];
    const float* w2     = (const float*)d_in[4];
    const float* b2     = (const float*)d_in[5];

    float* out = (float*)d_out;
    float* out_output  = out + OFF_OUTPUT;
    float* out_attsp   = out + OFF_ATTSP;
    float* out_inflat  = out + OFF_INFLAT;
    float* out_memnorm = out + OFF_MEMNORM;
    float* out_att     = out + OFF_ATT;

    cudaFuncSetAttribute((const void*)k1_mlp1_input,
                         cudaFuncAttributeMaxDynamicSharedMemorySize, GEMM_SMEM_BYTES);
    cudaFuncSetAttribute((const void*)k2_mlp2_input,
                         cudaFuncAttributeMaxDynamicSharedMemorySize, GEMM_SMEM_BYTES);
    cudaFuncSetAttribute((const void*)gemm3_kernel,
                         cudaFuncAttributeMaxDynamicSharedMemorySize, HGEMM_SMEM_BYTES);
    cudaFuncSetAttribute((const void*)k4_gemm4_tail,
                         cudaFuncAttributeMaxDynamicSharedMemorySize, HGEMM_SMEM_BYTES);

    // K1: MLP layer 1 || input processing (rows 0..8191)
    k1_mlp1_input<<<148, 256, GEMM_SMEM_BYTES>>>(memory, w1, b1, x, out_inflat);
    // K2: MLP layer 2 || input processing (rows 8192..16383)
    k2_mlp2_input<<<148, 256, GEMM_SMEM_BYTES>>>(w2, b2, x, out_inflat);
    // memory_norm (f32 + fp16 + fp16-transposed)
    rownorm_t_kernel<<<MDIM, 256>>>(out_memnorm);
    // addressing logits -> att section
    gemm3_kernel<<<512, 256, HGEMM_SMEM_BYTES>>>(out_att);
    // softmax + shrink + renorm (+ fp16 att)
    softmax_shrink_kernel<<<R_ROWS / 8, 256>>>(out_att);
    // output GEMM + fused channel-mean/broadcast
    k4_gemm4_tail<<<1152, 256, HGEMM_SMEM_BYTES>>>(out_output, out_attsp);
}

// round 9
// speedup vs baseline: 5.1932x; 1.0049x over previous
#include <cuda_runtime.h>
#include <cuda_fp16.h>
#include <cstdint>
#include <math.h>

// Problem constants
#define R_ROWS  16384   // N*C
#define SPATIAL 1024    // H*W
#define MDIM    512     // mem_dim
#define HIDDIM  512     // spatial/2

// d_out section offsets (floats)
#define OFF_OUTPUT   ((size_t)0)
#define OFF_ATTSP    ((size_t)16777216)
#define OFF_INFLAT   ((size_t)33554432)
#define OFF_MEMNORM  ((size_t)50331648)
#define OFF_ATT      ((size_t)50855936)

// Device scratch (allocation-free)
__device__ float  g_h[MDIM * HIDDIM];
__device__ float  g_memproc[MDIM * SPATIAL];
__device__ float  g_invnorm[R_ROWS];
__device__ __half g_xh[(size_t)R_ROWS * SPATIAL];    // fp16 x
__device__ __half g_mnh[MDIM * SPATIAL];             // fp16 memory_norm
__device__ __half g_mnTh[SPATIAL * MDIM];            // fp16 memory_norm^T
__device__ __half g_atth[(size_t)R_ROWS * MDIM];     // fp16 att

// ============================================================================
// mma.sync helpers (sm_80+ — base compute_103 target safe)
// ============================================================================
__device__ __forceinline__ void mma8_tf32(float* c, uint32_t a0, uint32_t a1,
                                          uint32_t a2, uint32_t a3,
                                          uint32_t b0, uint32_t b1) {
    asm volatile(
        "mma.sync.aligned.m16n8k8.row.col.f32.tf32.tf32.f32 "
        "{%0,%1,%2,%3}, {%4,%5,%6,%7}, {%8,%9}, {%0,%1,%2,%3};"
        : "+f"(c[0]), "+f"(c[1]), "+f"(c[2]), "+f"(c[3])
        : "r"(a0), "r"(a1), "r"(a2), "r"(a3), "r"(b0), "r"(b1));
}

__device__ __forceinline__ void mma16_f16(float* c, uint32_t a0, uint32_t a1,
                                          uint32_t a2, uint32_t a3,
                                          uint32_t b0, uint32_t b1) {
    asm volatile(
        "mma.sync.aligned.m16n8k16.row.col.f32.f16.f16.f32 "
        "{%0,%1,%2,%3}, {%4,%5,%6,%7}, {%8,%9}, {%0,%1,%2,%3};"
        : "+f"(c[0]), "+f"(c[1]), "+f"(c[2]), "+f"(c[3])
        : "r"(a0), "r"(a1), "r"(a2), "r"(a3), "r"(b0), "r"(b1));
}

__device__ __forceinline__ void ldmx4(uint32_t& r0, uint32_t& r1,
                                      uint32_t& r2, uint32_t& r3, uint32_t addr) {
    asm volatile("ldmatrix.sync.aligned.m8n8.x4.shared.b16 {%0,%1,%2,%3}, [%4];"
                 : "=r"(r0), "=r"(r1), "=r"(r2), "=r"(r3) : "r"(addr));
}

__device__ __forceinline__ uint32_t tf32_hi(float x) {
    uint32_t h;
    asm("cvt.rna.tf32.f32 %0, %1;" : "=r"(h) : "f"(x));
    return h;
}

__device__ __forceinline__ void cp16(uint32_t dst, const void* src) {
    asm volatile("cp.async.cg.shared.global [%0], [%1], 16;" :: "r"(dst), "l"(src));
}

__device__ __forceinline__ uint32_t pack_half2(float a, float b) {
    __half2 h = __floats2half2_rn(a, b);
    return *reinterpret_cast<uint32_t*>(&h);
}

__device__ __forceinline__ float warp_sum(float v) {
#pragma unroll
    for (int o = 16; o > 0; o >>= 1) v += __shfl_xor_sync(0xffffffffu, v, o);
    return v;
}
__device__ __forceinline__ float warp_max(float v) {
#pragma unroll
    for (int o = 16; o > 0; o >>= 1) v = fmaxf(v, __shfl_xor_sync(0xffffffffu, v, o));
    return v;
}

// ============================================================================
// tf32 NT GEMM tile (device fn) — precision-critical MLP path.
// CTA tile 128x128xBK32, 8 warps, 3-stage cp.async, 1 barrier per chunk.
// ============================================================================
#define SSTRIDE 36
#define TILEF   (128 * SSTRIDE)
#define STAGEF  (2 * TILEF)
#define GEMM_SMEM_BYTES (3 * STAGEF * 4)

__device__ void mlp_tile(
    int Ntot, int K,
    const float* __restrict__ A, const float* __restrict__ B,
    float* __restrict__ C, const float* __restrict__ bias,
    int bm, int bn)
{
    extern __shared__ float smf[];
    const uint32_t sbase = (uint32_t)__cvta_generic_to_shared(smf);
    const int tid  = threadIdx.x;
    const int wid  = tid >> 5;
    const int lane = tid & 31;
    const int wm   = wid & 1;
    const int wn   = wid >> 1;
    const int tr   = lane >> 2;
    const int tc   = lane & 3;

    const float* At = A + (size_t)bm * K;
    const float* Bt = B + (size_t)bn * K;
    const int nk = K >> 5;

    auto load_stage = [&](int st, int kc) {
        const uint32_t so = sbase + (uint32_t)(st * STAGEF * 4);
#pragma unroll
        for (int i = 0; i < 4; i++) {
            int u = tid + i * 256;
            int row = u >> 3;
            int seg = (u & 7) * 4;
            cp16(so + (uint32_t)((row * SSTRIDE + seg) * 4),
                 At + (size_t)row * K + kc * 32 + seg);
            cp16(so + (uint32_t)((TILEF + row * SSTRIDE + seg) * 4),
                 Bt + (size_t)row * K + kc * 32 + seg);
        }
        asm volatile("cp.async.commit_group;" ::: "memory");
    };

    float c[4][4][4];
#pragma unroll
    for (int mf = 0; mf < 4; mf++)
#pragma unroll
        for (int nf = 0; nf < 4; nf++)
#pragma unroll
            for (int q = 0; q < 4; q++) c[mf][nf][q] = 0.0f;

    load_stage(0, 0);
    load_stage(1, 1);

    for (int s = 0; s < nk; ++s) {
        if (s + 1 < nk) asm volatile("cp.async.wait_group 1;" ::: "memory");
        else            asm volatile("cp.async.wait_group 0;" ::: "memory");
        __syncthreads();
        if (s + 2 < nk) load_stage((s + 2) % 3, s + 2);

        const float* As = smf + (s % 3) * STAGEF;
        const float* Bs = As + TILEF;

#pragma unroll
        for (int kk = 0; kk < 4; kk++) {
            const int kb = kk * 8;
            uint32_t ah[4][4], bh[4][2];
#pragma unroll
            for (int mf = 0; mf < 4; mf++) {
                const int r0 = wm * 64 + mf * 16 + tr;
                ah[mf][0] = tf32_hi(As[r0 * SSTRIDE + kb + tc]);
                ah[mf][1] = tf32_hi(As[(r0 + 8) * SSTRIDE + kb + tc]);
                ah[mf][2] = tf32_hi(As[r0 * SSTRIDE + kb + tc + 4]);
                ah[mf][3] = tf32_hi(As[(r0 + 8) * SSTRIDE + kb + tc + 4]);
            }
#pragma unroll
            for (int nf = 0; nf < 4; nf++) {
                const int n0 = wn * 32 + nf * 8 + tr;
                bh[nf][0] = tf32_hi(Bs[n0 * SSTRIDE + kb + tc]);
                bh[nf][1] = tf32_hi(Bs[n0 * SSTRIDE + kb + tc + 4]);
            }
#pragma unroll
            for (int mf = 0; mf < 4; mf++)
#pragma unroll
                for (int nf = 0; nf < 4; nf++)
                    mma8_tf32(c[mf][nf], ah[mf][0], ah[mf][1], ah[mf][2], ah[mf][3],
                              bh[nf][0], bh[nf][1]);
        }
    }

#pragma unroll
    for (int mf = 0; mf < 4; mf++) {
        const int r0g = bm + wm * 64 + mf * 16 + tr;
#pragma unroll
        for (int nf = 0; nf < 4; nf++) {
            const int cg = bn + wn * 32 + nf * 8 + 2 * tc;
            float bb0 = bias[cg], bb1 = bias[cg + 1];
            float v0 = fmaxf(c[mf][nf][0] + bb0, 0.0f);
            float v1 = fmaxf(c[mf][nf][1] + bb1, 0.0f);
            float v2 = fmaxf(c[mf][nf][2] + bb0, 0.0f);
            float v3 = fmaxf(c[mf][nf][3] + bb1, 0.0f);
            *(float2*)&C[(size_t)r0g * Ntot + cg]       = make_float2(v0, v1);
            *(float2*)&C[(size_t)(r0g + 8) * Ntot + cg] = make_float2(v2, v3);
        }
    }
}

// ============================================================================
// fp16 NT GEMM tile: 4-stage pipeline (prefetch distance 3), smem 80KB,
// 2 CTAs/SM (regs capped by __launch_bounds__(256,2)).
// ============================================================================
#define SSW      20
#define HTILEW   (128 * SSW)
#define HSTAGEW  (2 * HTILEW)
#define HGEMM_SMEM_BYTES (4 * HSTAGEW * 4)   // 81920 B

template <bool ROWSCALE>
__device__ void gemm16_tile(
    int Ntot, int K,
    const __half* __restrict__ A, const __half* __restrict__ B,
    float* __restrict__ C, const float* __restrict__ rowscale,
    int bm, int bn)
{
    extern __shared__ uint32_t smw[];
    const uint32_t sbase = (uint32_t)__cvta_generic_to_shared(smw);
    const int tid  = threadIdx.x;
    const int wid  = tid >> 5;
    const int lane = tid & 31;
    const int wm   = wid & 1;
    const int wn   = wid >> 1;
    const int tr   = lane >> 2;
    const int tc   = lane & 3;

    const __half* At = A + (size_t)bm * K;
    const __half* Bt = B + (size_t)bn * K;
    const int nk = K >> 5;     // >= 16 here

    const int q = lane >> 3;
    const int rsub = lane & 7;
    const int arow = wm * 64 + rsub + (q & 1) * 8;
    const int acolw = (q >> 1) * 4;
    const int brow = wn * 32 + rsub + (q >> 1) * 8;
    const int bcolw = (q & 1) * 4;

    auto load_stage = [&](int st, int kc) {
        const uint32_t so = sbase + (uint32_t)(st * HSTAGEW * 4);
#pragma unroll
        for (int i = 0; i < 2; i++) {
            int u = tid + i * 256;
            int row = u >> 2;
            int seg = (u & 3) * 4;
            cp16(so + (uint32_t)((row * SSW + seg) * 4),
                 At + (size_t)row * K + kc * 32 + seg * 2);
            cp16(so + (uint32_t)((HTILEW + row * SSW + seg) * 4),
                 Bt + (size_t)row * K + kc * 32 + seg * 2);
        }
        asm volatile("cp.async.commit_group;" ::: "memory");
    };

    float c[4][4][4];
#pragma unroll
    for (int mf = 0; mf < 4; mf++)
#pragma unroll
        for (int nf = 0; nf < 4; nf++)
#pragma unroll
            for (int qq = 0; qq < 4; qq++) c[mf][nf][qq] = 0.0f;

    load_stage(0, 0);
    load_stage(1, 1);
    load_stage(2, 2);

    for (int s = 0; s < nk; ++s) {
        // wait until stage s's load group is complete
        if (s + 2 < nk)      asm volatile("cp.async.wait_group 2;" ::: "memory");
        else if (s + 1 < nk) asm volatile("cp.async.wait_group 1;" ::: "memory");
        else                 asm volatile("cp.async.wait_group 0;" ::: "memory");
        __syncthreads();
        if (s + 3 < nk) load_stage((s + 3) & 3, s + 3);

        const uint32_t stage = sbase + (uint32_t)((s & 3) * HSTAGEW * 4);
        const uint32_t aAddr0 = stage + (uint32_t)((arow * SSW + acolw) * 4);
        const uint32_t bAddr0 = stage + (uint32_t)((HTILEW + brow * SSW + bcolw) * 4);

#pragma unroll
        for (int kk = 0; kk < 2; kk++) {
            const uint32_t kboff = (uint32_t)(kk * 8 * 4);
            uint32_t a[4][4], b[4][2];
#pragma unroll
            for (int mf = 0; mf < 4; mf++)
                ldmx4(a[mf][0], a[mf][1], a[mf][2], a[mf][3],
                      aAddr0 + kboff + (uint32_t)(mf * 16 * SSW * 4));
#pragma unroll
            for (int nf2 = 0; nf2 < 2; nf2++)
                ldmx4(b[2 * nf2][0], b[2 * nf2][1], b[2 * nf2 + 1][0], b[2 * nf2 + 1][1],
                      bAddr0 + kboff + (uint32_t)(nf2 * 16 * SSW * 4));
#pragma unroll
            for (int mf = 0; mf < 4; mf++)
#pragma unroll
                for (int nf = 0; nf < 4; nf++)
                    mma16_f16(c[mf][nf], a[mf][0], a[mf][1], a[mf][2], a[mf][3],
                              b[nf][0], b[nf][1]);
        }
    }

#pragma unroll
    for (int mf = 0; mf < 4; mf++) {
        const int r0g = bm + wm * 64 + mf * 16 + tr;
        const float rs0 = ROWSCALE ? rowscale[r0g] : 1.0f;
        const float rs1 = ROWSCALE ? rowscale[r0g + 8] : 1.0f;
#pragma unroll
        for (int nf = 0; nf < 4; nf++) {
            const int cg = bn + wn * 32 + nf * 8 + 2 * tc;
            float v0 = c[mf][nf][0], v1 = c[mf][nf][1];
            float v2 = c[mf][nf][2], v3 = c[mf][nf][3];
            if (ROWSCALE) { v0 *= rs0; v1 *= rs0; v2 *= rs1; v3 *= rs1; }
            *(float2*)&C[(size_t)r0g * Ntot + cg]       = make_float2(v0, v1);
            *(float2*)&C[(size_t)(r0g + 8) * Ntot + cg] = make_float2(v2, v3);
        }
    }
}

// ============================================================================
// Fused input processing: copy x -> input_flat, fp16(x) -> g_xh, invnorm.
// ============================================================================
__device__ void input_rows(const float* __restrict__ x, float* __restrict__ inflat,
                           int gwarp, int nwarps, int base) {
    const int lane = threadIdx.x & 31;
    for (int row = base + gwarp; row < base + 8192; row += nwarps) {
        const float4* p = (const float4*)(x + (size_t)row * SPATIAL);
        float4* of = (float4*)(inflat + (size_t)row * SPATIAL);
        uint2*  xo = (uint2*)(g_xh + (size_t)row * SPATIAL);
        float s = 0.0f;
#pragma unroll
        for (int i = 0; i < 8; i++) {
            float4 v = p[lane + 32 * i];
            s += v.x * v.x + v.y * v.y + v.z * v.z + v.w * v.w;
            of[lane + 32 * i] = v;
            xo[lane + 32 * i] = make_uint2(pack_half2(v.x, v.y), pack_half2(v.z, v.w));
        }
        s = warp_sum(s);
        if (lane == 0) g_invnorm[row] = 1.0f / fmaxf(sqrtf(s), 1e-12f);
    }
}

// K1: MLP1 (16 CTAs) + input rows 0..8191 (132 CTAs)
__global__ void __launch_bounds__(256, 1) k1_mlp1_input(
    const float* __restrict__ memory, const float* __restrict__ w1,
    const float* __restrict__ b1, const float* __restrict__ x,
    float* __restrict__ inflat)
{
    const int b = blockIdx.x;
    if (b < 16) {
        mlp_tile(HIDDIM, SPATIAL, memory, w1, g_h, b1, (b >> 2) * 128, (b & 3) * 128);
    } else {
        const int gwarp = (b - 16) * 8 + (threadIdx.x >> 5);
        input_rows(x, inflat, gwarp, 132 * 8, 0);
    }
}

// K2: MLP2 (32 CTAs) + input rows 8192..16383 (116 CTAs)
__global__ void __launch_bounds__(256, 1) k2_mlp2_input(
    const float* __restrict__ w2, const float* __restrict__ b2,
    const float* __restrict__ x, float* __restrict__ inflat)
{
    const int b = blockIdx.x;
    if (b < 32) {
        mlp_tile(SPATIAL, HIDDIM, g_h, w2, g_memproc, b2, (b >> 3) * 128, (b & 7) * 128);
    } else {
        const int gwarp = (b - 32) * 8 + (threadIdx.x >> 5);
        input_rows(x, inflat, gwarp, 116 * 8, 8192);
    }
}

// ============================================================================
// rownorm + fp16 + transposed fp16 in one pass. Block per row.
// ============================================================================
__global__ __launch_bounds__(256) void rownorm_t_kernel(float* __restrict__ dst) {
    __shared__ float sm[8];
    const int row  = blockIdx.x;
    const int tid  = threadIdx.x;
    const int lane = tid & 31;
    const int w    = tid >> 5;
    const float4* p = (const float4*)(g_memproc + (size_t)row * SPATIAL);
    float4 v = p[tid];
    float s = v.x * v.x + v.y * v.y + v.z * v.z + v.w * v.w;
    s = warp_sum(s);
    if (lane == 0) sm[w] = s;
    __syncthreads();
    float tot = 0.0f;
#pragma unroll
    for (int i = 0; i < 8; i++) tot += sm[i];
    const float sc = 1.0f / fmaxf(sqrtf(tot), 1e-12f);
    float4 o = make_float4(v.x * sc, v.y * sc, v.z * sc, v.w * sc);
    ((float4*)(dst + (size_t)row * SPATIAL))[tid] = o;
    ((uint2*)(g_mnh + (size_t)row * SPATIAL))[tid] =
        make_uint2(pack_half2(o.x, o.y), pack_half2(o.z, o.w));
    g_mnTh[(size_t)(4 * tid + 0) * MDIM + row] = __float2half_rn(o.x);
    g_mnTh[(size_t)(4 * tid + 1) * MDIM + row] = __float2half_rn(o.y);
    g_mnTh[(size_t)(4 * tid + 2) * MDIM + row] = __float2half_rn(o.z);
    g_mnTh[(size_t)(4 * tid + 3) * MDIM + row] = __float2half_rn(o.w);
}

// ============================================================================
// GEMM3: S = diag(invnorm) * (xh @ mnh^T) -> att (f32)
// ============================================================================
__global__ void __launch_bounds__(256, 2) gemm3_kernel(float* __restrict__ att) {
    const int b = blockIdx.x;
    gemm16_tile<true>(MDIM, SPATIAL, g_xh, g_mnh, att, g_invnorm,
                      (b >> 2) * 128, (b & 3) * 128);
}

// ============================================================================
// softmax + shrink + L1 renorm, in place (f32) + fp16 copy. Warp per row.
// ============================================================================
__global__ __launch_bounds__(256) void softmax_shrink_kernel(float* __restrict__ S) {
    const int row  = blockIdx.x * 8 + (threadIdx.x >> 5);
    const int lane = threadIdx.x & 31;
    float4* p = (float4*)(S + (size_t)row * MDIM);
    uint2* ph = (uint2*)(g_atth + (size_t)row * MDIM);
    float4 v[4];
#pragma unroll
    for (int i = 0; i < 4; i++) v[i] = p[lane + 32 * i];
    float m = -INFINITY;
#pragma unroll
    for (int i = 0; i < 4; i++)
        m = fmaxf(m, fmaxf(fmaxf(v[i].x, v[i].y), fmaxf(v[i].z, v[i].w)));
    m = warp_max(m);
    float s = 0.0f;
#pragma unroll
    for (int i = 0; i < 4; i++) {
        v[i].x = expf(v[i].x - m); v[i].y = expf(v[i].y - m);
        v[i].z = expf(v[i].z - m); v[i].w = expf(v[i].w - m);
        s += v[i].x + v[i].y + v[i].z + v[i].w;
    }
    s = warp_sum(s);
    const float inv = 1.0f / s;
    float t = 0.0f;
#pragma unroll
    for (int i = 0; i < 4; i++) {
        v[i].x = fmaxf(v[i].x * inv - 0.0025f, 0.0f);
        v[i].y = fmaxf(v[i].y * inv - 0.0025f, 0.0f);
        v[i].z = fmaxf(v[i].z * inv - 0.0025f, 0.0f);
        v[i].w = fmaxf(v[i].w * inv - 0.0025f, 0.0f);
        t += v[i].x + v[i].y + v[i].z + v[i].w;
    }
    t = warp_sum(t);
    const float inv2 = 1.0f / fmaxf(t, 1e-12f);
#pragma unroll
    for (int i = 0; i < 4; i++) {
        v[i].x *= inv2; v[i].y *= inv2; v[i].z *= inv2; v[i].w *= inv2;
        p[lane + 32 * i] = v[i];
        ph[lane + 32 * i] = make_uint2(pack_half2(v[i].x, v[i].y),
                                       pack_half2(v[i].z, v[i].w));
    }
}

// ============================================================================
// K4: tail blocks (chanmean+bcast, 128) first, then GEMM4 (1024 blocks)
// ============================================================================
__global__ void __launch_bounds__(256, 2) k4_gemm4_tail(
    float* __restrict__ outp, float* __restrict__ attsp)
{
    const int b = blockIdx.x;
    if (b >= 128) {
        const int g = b - 128;
        gemm16_tile<false>(SPATIAL, MDIM, g_atth, g_mnTh, outp, nullptr,
                           (g >> 3) * 128, (g & 7) * 128);
        return;
    }
    extern __shared__ float sf[];
    const int n  = b >> 2;
    const int mg = b & 3;
    const int t  = threadIdx.x;
    const int m  = t & 127;
    const int ch = t >> 7;
    const __half* base = g_atth + ((size_t)(n * 512 + ch * 256)) * MDIM + mg * 128 + m;
    float s = 0.0f;
#pragma unroll 4
    for (int c = 0; c < 256; c++) s += __half2float(base[(size_t)c * MDIM]);
    sf[t] = s;
    __syncthreads();
    if (t < 128) sf[256 + t] = (sf[t] + sf[t + 128]) * (1.0f / 512.0f);
    __syncthreads();
    float* dst0 = attsp + ((size_t)(n * MDIM + mg * 128)) * SPATIAL;
    for (int m2 = 0; m2 < 128; m2++) {
        const float v = sf[256 + m2];
        ((float4*)(dst0 + (size_t)m2 * SPATIAL))[t] = make_float4(v, v, v, v);
    }
}

// ============================================================================
extern "C" void kernel_launch(void* const* d_in, const int* in_sizes, int n_in,
                              void* d_out, int out_size) {
    (void)in_sizes; (void)n_in; (void)out_size;
    const float* x      = (const float*)d_in[0];
    const float* memory = (const float*)d_in[1];
    const float* w1     = (const float*)d_in[2];
    const float* b1     = (const float*)d_in[3];
    const float* w2     = (const float*)d_in[4];
    const float* b2     = (const float*)d_in[5];

    float* out = (float*)d_out;
    float* out_output  = out + OFF_OUTPUT;
    float* out_attsp   = out + OFF_ATTSP;
    float* out_inflat  = out + OFF_INFLAT;
    float* out_memnorm = out + OFF_MEMNORM;
    float* out_att     = out + OFF_ATT;

    cudaFuncSetAttribute((const void*)k1_mlp1_input,
                         cudaFuncAttributeMaxDynamicSharedMemorySize, GEMM_SMEM_BYTES);
    cudaFuncSetAttribute((const void*)k2_mlp2_input,
                         cudaFuncAttributeMaxDynamicSharedMemorySize, GEMM_SMEM_BYTES);
    cudaFuncSetAttribute((const void*)gemm3_kernel,
                         cudaFuncAttributeMaxDynamicSharedMemorySize, HGEMM_SMEM_BYTES);
    cudaFuncSetAttribute((const void*)k4_gemm4_tail,
                         cudaFuncAttributeMaxDynamicSharedMemorySize, HGEMM_SMEM_BYTES);

    // K1: MLP layer 1 || input processing (rows 0..8191)
    k1_mlp1_input<<<148, 256, GEMM_SMEM_BYTES>>>(memory, w1, b1, x, out_inflat);
    // K2: MLP layer 2 || input processing (rows 8192..16383)
    k2_mlp2_input<<<148, 256, GEMM_SMEM_BYTES>>>(w2, b2, x, out_inflat);
    // memory_norm (f32 + fp16 + fp16-transposed)
    rownorm_t_kernel<<<MDIM, 256>>>(out_memnorm);
    // addressing logits -> att section
    gemm3_kernel<<<512, 256, HGEMM_SMEM_BYTES>>>(out_att);
    // softmax + shrink + renorm (+ fp16 att)
    softmax_shrink_kernel<<<R_ROWS / 8, 256>>>(out_att);
    // output GEMM + fused channel-mean/broadcast
    k4_gemm4_tail<<<1152, 256, HGEMM_SMEM_BYTES>>>(out_output, out_attsp);
}